// round 2
// baseline (speedup 1.0000x reference)
#include <cuda_runtime.h>
#include <math.h>

#define B_ 65536
#define F_ 64
#define L_ 32
#define E_ 512

#define BM 128
#define BN 128
#define NTHREADS 256

// shared memory layout (float offsets)
#define OFF_SF   0                         // sFactors [128][65]
#define OFF_SW1  (OFF_SF + 128*65)         // sW1 [32*32]
#define OFF_SENC (OFF_SW1 + 1024)          // sEnc [32][130]
#define OFF_SHW  (OFF_SENC + 32*130)       // sHw  [32][132] (transposed: [j][row])
#define OFF_SW2  (OFF_SHW + 32*132)        // sW2  [32][132] ([j][col])
#define SMEM_FLOATS (OFF_SW2 + 32*132)

__device__ float g_w[F_];
__device__ float g_wb2[E_];

// ---------------------------------------------------------------------------
// Prologue: softmax(w_raw) -> g_w (+ output tail), w @ b2 -> g_wb2
// ---------------------------------------------------------------------------
__global__ void prologue_kernel(const float* __restrict__ w_raw,
                                const float* __restrict__ b2,
                                float* __restrict__ d_out, int out_size) {
    __shared__ float sw[F_];
    int tid = threadIdx.x;
    if (tid < F_) sw[tid] = w_raw[tid];
    __syncthreads();

    // redundant per-thread reduction over 64 elements (cheap)
    float m = -INFINITY;
    for (int f = 0; f < F_; f++) m = fmaxf(m, sw[f]);
    float s = 0.f;
    for (int f = 0; f < F_; f++) s += expf(sw[f] - m);
    float inv = 1.f / s;
    __syncthreads();   // everyone done reading raw values

    if (tid < F_) {
        float wv = expf(sw[tid] - m) * inv;
        sw[tid] = wv;                 // overwrite with softmax value
        g_w[tid] = wv;
        if (out_size >= B_ * E_ + F_) d_out[B_ * E_ + tid] = wv;
    }
    __syncthreads();

    for (int e = tid; e < E_; e += blockDim.x) {
        float acc = 0.f;
        for (int f = 0; f < F_; f++) acc = fmaf(sw[f], b2[f * E_ + e], acc);
        g_wb2[e] = acc;
    }
}

// ---------------------------------------------------------------------------
// Fused main kernel: enc -> W1 -> LN -> GELU -> *w[f] -> GEMM vs W2 tile
// Grid: (B/BM = 512, E/BN = 4), 256 threads.
// ---------------------------------------------------------------------------
__global__ void __launch_bounds__(NTHREADS)
batch_encoder_main_kernel(const float* __restrict__ bf,
                          const float* __restrict__ W1,
                          const float* __restrict__ b1,
                          const float* __restrict__ gamma,
                          const float* __restrict__ beta,
                          const float* __restrict__ W2,
                          float* __restrict__ out) {
    extern __shared__ float sm[];
    float* sF   = sm + OFF_SF;
    float* sW1  = sm + OFF_SW1;
    float* sEnc = sm + OFF_SENC;
    float* sHw  = sm + OFF_SHW;
    float* sW2  = sm + OFF_SW2;

    const int tid = threadIdx.x;
    const int b0 = blockIdx.x * BM;
    const int e0 = blockIdx.y * BN;
    const int tx = tid & 15;     // 0..15  -> E columns
    const int ty = tid >> 4;     // 0..15  -> batch rows

    // stage-1b assignment: 2 threads per row, each computes 16 of 32 h values
    const int r1 = tid >> 1;           // row 0..127
    const int jbase = (tid & 1) * 16;  // 0 or 16

    // load the CTA's batch_factors tile [128][64] (padded to 65)
    for (int idx = tid; idx < BM * F_; idx += NTHREADS) {
        int r = idx >> 6, f = idx & 63;
        sF[r * 65 + f] = bf[(b0 + r) * F_ + f];
    }
    __syncthreads();

    float acc[8][8];
    #pragma unroll
    for (int mi = 0; mi < 8; mi++)
        #pragma unroll
        for (int ni = 0; ni < 8; ni++) acc[mi][ni] = 0.f;

    for (int f = 0; f < F_; f++) {
        // ---- phase A: load W1[f], W2[f] tile; compute enc rows ----
        #pragma unroll
        for (int k = 0; k < 4; k++) {
            int idx = tid + k * NTHREADS;           // 0..1023
            sW1[idx] = W1[f * (L_ * L_) + idx];
        }
        #pragma unroll
        for (int k = 0; k < 4; k++) {
            int idx = tid + k * NTHREADS;           // float4 index 0..1023
            int j = idx >> 5;
            int c4 = (idx & 31) << 2;
            *(float4*)(sW2 + j * 132 + c4) =
                *(const float4*)(W2 + (f * L_ + j) * E_ + e0 + c4);
        }
        if (tid < BM) {
            float x = sF[tid * 65 + f];
            float enc[2 * 16];
            float s, c;
            float p = 0.1f * x;                     // theta_0
            sincosf(p, &s, &c);
            enc[0] = s; enc[16] = c;
            // i=1..7 via double-angle (phase error ~1e-5, well under tolerance)
            #pragma unroll
            for (int i = 1; i < 8; i++) {
                float s2 = 2.f * s * c;
                float c2 = fmaf(-2.f * s, s, 1.f);
                s = s2; c = c2;
                enc[i] = s; enc[16 + i] = c;
            }
            // i=8..15 direct (large phase: match reference rounding exactly)
            #pragma unroll
            for (int i = 8; i < 16; i++) {
                float th = (0.1f * (float)(1 << i)) * x;
                sincosf(th, &s, &c);
                enc[i] = s; enc[16 + i] = c;
            }
            #pragma unroll
            for (int i = 0; i < 32; i++) sEnc[i * 130 + tid] = enc[i];
        }
        __syncthreads();

        // ---- phase B: h = enc @ W1 + b1; LayerNorm; GELU; * w[f] ----
        {
            float h[16];
            #pragma unroll
            for (int j = 0; j < 16; j++)
                h[j] = __ldg(&b1[f * L_ + jbase + j]);
            #pragma unroll
            for (int i = 0; i < 32; i++) {
                float e = sEnc[i * 130 + r1];
                #pragma unroll
                for (int j = 0; j < 16; j++)
                    h[j] = fmaf(e, sW1[i * 32 + jbase + j], h[j]);
            }
            float s1 = 0.f, s2 = 0.f;
            #pragma unroll
            for (int j = 0; j < 16; j++) {
                s1 += h[j];
                s2 = fmaf(h[j], h[j], s2);
            }
            s1 += __shfl_xor_sync(0xffffffffu, s1, 1);
            s2 += __shfl_xor_sync(0xffffffffu, s2, 1);
            float mean = s1 * (1.f / 32.f);
            float var  = s2 * (1.f / 32.f) - mean * mean;
            float rstd = rsqrtf(var + 1e-5f);
            float wf = g_w[f];
            #pragma unroll
            for (int j = 0; j < 16; j++) {
                float hn = (h[j] - mean) * rstd;
                hn = fmaf(hn, __ldg(&gamma[f * L_ + jbase + j]),
                              __ldg(&beta[f * L_ + jbase + j]));
                float g = 0.5f * hn * (1.f + erff(hn * 0.70710678118654752f));
                sHw[(jbase + j) * 132 + r1] = g * wf;
            }
        }
        __syncthreads();

        // ---- phase C: acc += Hw_tile^T-block @ W2_tile (8x8 microtile) ----
        #pragma unroll 4
        for (int j = 0; j < 32; j++) {
            float4 a0 = *(float4*)(sHw + j * 132 + ty * 8);
            float4 a1 = *(float4*)(sHw + j * 132 + ty * 8 + 4);
            float4 bA = *(float4*)(sW2 + j * 132 + tx * 4);
            float4 bB = *(float4*)(sW2 + j * 132 + 64 + tx * 4);
            float av[8] = {a0.x, a0.y, a0.z, a0.w, a1.x, a1.y, a1.z, a1.w};
            float bv[8] = {bA.x, bA.y, bA.z, bA.w, bB.x, bB.y, bB.z, bB.w};
            #pragma unroll
            for (int mi = 0; mi < 8; mi++)
                #pragma unroll
                for (int ni = 0; ni < 8; ni++)
                    acc[mi][ni] = fmaf(av[mi], bv[ni], acc[mi][ni]);
        }
        __syncthreads();
    }

    // ---- epilogue: add w@b2 bias, store ----
    float wb[8];
    #pragma unroll
    for (int ni = 0; ni < 4; ni++) {
        wb[ni]     = g_wb2[e0 + tx * 4 + ni];
        wb[ni + 4] = g_wb2[e0 + 64 + tx * 4 + ni];
    }
    #pragma unroll
    for (int mi = 0; mi < 8; mi++) {
        int row = b0 + ty * 8 + mi;
        float4 v0, v1;
        v0.x = acc[mi][0] + wb[0]; v0.y = acc[mi][1] + wb[1];
        v0.z = acc[mi][2] + wb[2]; v0.w = acc[mi][3] + wb[3];
        v1.x = acc[mi][4] + wb[4]; v1.y = acc[mi][5] + wb[5];
        v1.z = acc[mi][6] + wb[6]; v1.w = acc[mi][7] + wb[7];
        *(float4*)(out + row * E_ + e0 + tx * 4)      = v0;
        *(float4*)(out + row * E_ + e0 + 64 + tx * 4) = v1;
    }
}

// ---------------------------------------------------------------------------
extern "C" void kernel_launch(void* const* d_in, const int* in_sizes, int n_in,
                              void* d_out, int out_size) {
    const float* bf    = (const float*)d_in[0];   // batch_factors [B,F]
    const float* w_raw = (const float*)d_in[1];   // [F]
    const float* W1    = (const float*)d_in[2];   // [F,L,L]
    const float* b1    = (const float*)d_in[3];   // [F,L]
    const float* gamma = (const float*)d_in[4];   // [F,L]
    const float* beta  = (const float*)d_in[5];   // [F,L]
    const float* W2    = (const float*)d_in[6];   // [F,L,E]
    const float* b2    = (const float*)d_in[7];   // [F,E]
    float* out = (float*)d_out;

    prologue_kernel<<<1, 512>>>(w_raw, b2, out, out_size);

    size_t smem_bytes = SMEM_FLOATS * sizeof(float);  // ~87.9 KB
    cudaFuncSetAttribute(batch_encoder_main_kernel,
                         cudaFuncAttributeMaxDynamicSharedMemorySize,
                         (int)smem_bytes);
    dim3 grid(B_ / BM, E_ / BN);
    batch_encoder_main_kernel<<<grid, NTHREADS, smem_bytes>>>(
        bf, W1, b1, gamma, beta, W2, out);
}

// round 4
// speedup vs baseline: 2.7511x; 2.7511x over previous
#include <cuda_runtime.h>
#include <cuda_bf16.h>
#include <math.h>
#include <stdint.h>

#define B_ 65536
#define F_ 64
#define L_ 32
#define E_ 512

// ---------------- device scratch ----------------
__device__ float g_w[F_];
__device__ float g_wb2[E_];
// A: [b][f*64 + c]  c: 0..31 = bf16 hi of h*w, 32..63 = bf16 lo residual  (512MB)
__device__ __nv_bfloat16 g_A[(size_t)B_ * 4096];
// B: [f*64 + r][e]  r: 0..31 = bf16 hi of W2[f][r][e], 32..63 = lo        (4MB)
__device__ __nv_bfloat16 g_B[(size_t)F_ * 64 * E_];

// ---------------- asm helpers ----------------
__device__ __forceinline__ uint32_t smem_to_u32(const void* p) {
    uint32_t a;
    asm("{ .reg .u64 t; cvta.to.shared.u64 t, %1; cvt.u32.u64 %0, t; }" : "=r"(a) : "l"(p));
    return a;
}
__device__ __forceinline__ void cp_async16(uint32_t s, const void* g) {
    asm volatile("cp.async.cg.shared.global [%0], [%1], 16;" :: "r"(s), "l"(g));
}
#define CP_COMMIT() asm volatile("cp.async.commit_group;" ::: "memory")
#define CP_WAIT(n)  asm volatile("cp.async.wait_group %0;" :: "n"(n) : "memory")

__device__ __forceinline__ void ldsm_x4(uint32_t* r, uint32_t addr) {
    asm volatile("ldmatrix.sync.aligned.m8n8.x4.shared.b16 {%0,%1,%2,%3}, [%4];"
                 : "=r"(r[0]), "=r"(r[1]), "=r"(r[2]), "=r"(r[3]) : "r"(addr));
}
__device__ __forceinline__ void ldsm_x4_t(uint32_t* r, uint32_t addr) {
    asm volatile("ldmatrix.sync.aligned.m8n8.x4.trans.shared.b16 {%0,%1,%2,%3}, [%4];"
                 : "=r"(r[0]), "=r"(r[1]), "=r"(r[2]), "=r"(r[3]) : "r"(addr));
}
__device__ __forceinline__ void mma_bf16(float& d0, float& d1, float& d2, float& d3,
                                         uint32_t a0, uint32_t a1, uint32_t a2, uint32_t a3,
                                         uint32_t b0, uint32_t b1) {
    asm volatile("mma.sync.aligned.m16n8k16.row.col.f32.bf16.bf16.f32 "
                 "{%0,%1,%2,%3}, {%4,%5,%6,%7}, {%8,%9}, {%0,%1,%2,%3};"
                 : "+f"(d0), "+f"(d1), "+f"(d2), "+f"(d3)
                 : "r"(a0), "r"(a1), "r"(a2), "r"(a3), "r"(b0), "r"(b1));
}

// ---------------------------------------------------------------------------
// Prologue: softmax(w_raw) -> g_w (+ output tail), w @ b2 -> g_wb2
// ---------------------------------------------------------------------------
__global__ void prologue_kernel(const float* __restrict__ w_raw,
                                const float* __restrict__ b2,
                                float* __restrict__ d_out, int out_size) {
    __shared__ float sw[F_];
    int tid = threadIdx.x;
    if (tid < F_) sw[tid] = w_raw[tid];
    __syncthreads();
    float m = -INFINITY;
    for (int f = 0; f < F_; f++) m = fmaxf(m, sw[f]);
    float s = 0.f;
    for (int f = 0; f < F_; f++) s += expf(sw[f] - m);
    float inv = 1.f / s;
    __syncthreads();
    if (tid < F_) {
        float wv = expf(sw[tid] - m) * inv;
        sw[tid] = wv;
        g_w[tid] = wv;
        if (out_size >= B_ * E_ + F_) d_out[B_ * E_ + tid] = wv;
    }
    __syncthreads();
    for (int e = tid; e < E_; e += blockDim.x) {
        float acc = 0.f;
        for (int f = 0; f < F_; f++) acc = fmaf(sw[f], b2[f * E_ + e], acc);
        g_wb2[e] = acc;
    }
}

// ---------------------------------------------------------------------------
// Prep: W2[f][j][e] -> g_B hi rows (0..31) + lo rows (32..63)
// ---------------------------------------------------------------------------
__global__ void prep_w2_kernel(const float* __restrict__ W2) {
    int f = blockIdx.x;
    int e = threadIdx.x;
    const float* src = W2 + (size_t)f * L_ * E_ + e;
    __nv_bfloat16* dst = g_B + (size_t)(f * 64) * E_ + e;
    #pragma unroll
    for (int j = 0; j < 32; j++) {
        float a = src[(size_t)j * E_];
        __nv_bfloat16 h = __float2bfloat16(a);
        float r = a - __bfloat162float(h);
        dst[(size_t)j * E_]        = h;
        dst[(size_t)(32 + j) * E_] = __float2bfloat16(r);
    }
}

// ---------------------------------------------------------------------------
// Stage 1: enc -> W1 -> LN -> GELU -> *w[f]; emit bf16 hi/lo to g_A.
// grid = 512 (batch tiles of 128), block = 256.
// ---------------------------------------------------------------------------
#define S1_SF   0                  // 128*65 floats
#define S1_W1   (128*65)           // 1024
#define S1_ENC  (S1_W1 + 1024)     // 32*130
#define S1_FLOATS (S1_ENC + 32*130)

__global__ void __launch_bounds__(256)
stage1_kernel(const float* __restrict__ bf,
              const float* __restrict__ W1,
              const float* __restrict__ b1,
              const float* __restrict__ gamma,
              const float* __restrict__ beta) {
    extern __shared__ float sm[];
    float* sF   = sm + S1_SF;
    float* sW1  = sm + S1_W1;
    float* sEnc = sm + S1_ENC;

    const int tid = threadIdx.x;
    const int b0 = blockIdx.x * 128;
    const int r1 = tid >> 1;
    const int jbase = (tid & 1) * 16;

    for (int idx = tid; idx < 128 * F_; idx += 256) {
        int r = idx >> 6, f = idx & 63;
        sF[r * 65 + f] = bf[(size_t)(b0 + r) * F_ + f];
    }
    __syncthreads();

    #pragma unroll 1
    for (int f = 0; f < F_; f++) {
        #pragma unroll
        for (int k = 0; k < 4; k++)
            sW1[tid + k * 256] = W1[f * 1024 + tid + k * 256];
        if (tid < 128) {
            float x = sF[tid * 65 + f];
            float enc[32];
            float s, c;
            sincosf(0.1f * x, &s, &c);
            enc[0] = s; enc[16] = c;
            #pragma unroll
            for (int i = 1; i < 8; i++) {
                float s2 = 2.f * s * c;
                float c2 = fmaf(-2.f * s, s, 1.f);
                s = s2; c = c2;
                enc[i] = s; enc[16 + i] = c;
            }
            #pragma unroll
            for (int i = 8; i < 16; i++) {
                sincosf((0.1f * (float)(1 << i)) * x, &s, &c);
                enc[i] = s; enc[16 + i] = c;
            }
            #pragma unroll
            for (int i = 0; i < 32; i++) sEnc[i * 130 + tid] = enc[i];
        }
        __syncthreads();

        {
            float h[16];
            #pragma unroll
            for (int j = 0; j < 16; j++) h[j] = __ldg(&b1[f * L_ + jbase + j]);
            #pragma unroll
            for (int i = 0; i < 32; i++) {
                float e = sEnc[i * 130 + r1];
                #pragma unroll
                for (int j = 0; j < 16; j++)
                    h[j] = fmaf(e, sW1[i * 32 + jbase + j], h[j]);
            }
            float s1 = 0.f, s2 = 0.f;
            #pragma unroll
            for (int j = 0; j < 16; j++) { s1 += h[j]; s2 = fmaf(h[j], h[j], s2); }
            s1 += __shfl_xor_sync(0xffffffffu, s1, 1);
            s2 += __shfl_xor_sync(0xffffffffu, s2, 1);
            float mean = s1 * (1.f / 32.f);
            float var  = s2 * (1.f / 32.f) - mean * mean;
            float rstd = rsqrtf(var + 1e-5f);
            float wf = g_w[f];
            float a[16];
            #pragma unroll
            for (int j = 0; j < 16; j++) {
                float hn = (h[j] - mean) * rstd;
                hn = fmaf(hn, __ldg(&gamma[f * L_ + jbase + j]),
                              __ldg(&beta[f * L_ + jbase + j]));
                a[j] = 0.5f * hn * (1.f + erff(hn * 0.70710678118654752f)) * wf;
            }
            uint32_t hu[8], lu[8];
            #pragma unroll
            for (int jj = 0; jj < 8; jj++) {
                unsigned short u0 = __bfloat16_as_ushort(__float2bfloat16(a[2 * jj]));
                unsigned short u1 = __bfloat16_as_ushort(__float2bfloat16(a[2 * jj + 1]));
                hu[jj] = (uint32_t)u0 | ((uint32_t)u1 << 16);
                float q0 = a[2 * jj]     - __bfloat162float(__ushort_as_bfloat16(u0));
                float q1 = a[2 * jj + 1] - __bfloat162float(__ushort_as_bfloat16(u1));
                lu[jj] = (uint32_t)__bfloat16_as_ushort(__float2bfloat16(q0)) |
                         ((uint32_t)__bfloat16_as_ushort(__float2bfloat16(q1)) << 16);
            }
            size_t base = (size_t)(b0 + r1) * 4096 + f * 64 + jbase;
            uint4* ph = (uint4*)(g_A + base);
            ph[0] = make_uint4(hu[0], hu[1], hu[2], hu[3]);
            ph[1] = make_uint4(hu[4], hu[5], hu[6], hu[7]);
            uint4* pl = (uint4*)(g_A + base + 32);
            pl[0] = make_uint4(lu[0], lu[1], lu[2], lu[3]);
            pl[1] = make_uint4(lu[4], lu[5], lu[6], lu[7]);
        }
        __syncthreads();   // protect sW1/sEnc before next f
    }
}

// ---------------------------------------------------------------------------
// Stage 2 GEMM: C = sum_f Ah.Bh + Al.Bh + Ah.Bl   (mma.sync bf16, fp32 accum)
// grid = (4 e-tiles, 512 b-tiles), block = 256 (8 warps, 64x32 each).
// 3-stage cp.async pipeline; A tile 128x64 bf16 (16KB), B tile 64x128 (16KB).
// ---------------------------------------------------------------------------
#define NSTAGE 3
#define STAGE_BYTES 32768

__global__ void __launch_bounds__(256, 2)
gemm_kernel(float* __restrict__ out) {
    extern __shared__ char smem[];
    const uint32_t sb = smem_to_u32(smem);
    const int tid = threadIdx.x, wid = tid >> 5, lane = tid & 31;
    const int wm = wid & 1, wn = wid >> 1;
    const int e0 = blockIdx.x * 128, b0 = blockIdx.y * 128;
    const int lr = lane & 15, lc = lane >> 4;

    float d[4][4][4];
    #pragma unroll
    for (int mi = 0; mi < 4; mi++)
        #pragma unroll
        for (int nf = 0; nf < 4; nf++)
            #pragma unroll
            for (int q = 0; q < 4; q++) d[mi][nf][q] = 0.f;

    auto issue_tile = [&](int f) {
        uint32_t s = sb + (f % NSTAGE) * STAGE_BYTES;
        const char* gA0 = (const char*)(g_A + (size_t)b0 * 4096 + f * 64);
        #pragma unroll
        for (int k = 0; k < 4; k++) {
            int c = tid + k * 256;           // 0..1023
            int r = c >> 3, off = (c & 7) * 16;
            cp_async16(s + r * 128 + (off ^ ((r & 7) << 4)),
                       gA0 + (size_t)r * 8192 + off);
        }
        const char* gB0 = (const char*)(g_B + (size_t)(f * 64) * E_ + e0);
        uint32_t sB = s + 16384;
        #pragma unroll
        for (int k = 0; k < 4; k++) {
            int c = tid + k * 256;           // 0..1023
            int kr = c >> 4, off = (c & 15) * 16;
            cp_async16(sB + kr * 256 + (off ^ ((kr & 7) << 4)),
                       gB0 + (size_t)kr * 1024 + off);
        }
    };

    issue_tile(0); CP_COMMIT();
    issue_tile(1); CP_COMMIT();
    issue_tile(2); CP_COMMIT();

    #pragma unroll 1
    for (int f = 0; f < F_; f++) {
        CP_WAIT(2);
        __syncthreads();
        const uint32_t aA = sb + (f % NSTAGE) * STAGE_BYTES;
        const uint32_t aB = aA + 16384;

        #pragma unroll
        for (int p = 0; p < 3; p++) {
            const int ak0 = (p == 1) ? 32 : 0;
            const int bk0 = (p == 2) ? 32 : 0;
            #pragma unroll
            for (int ks = 0; ks < 2; ks++) {
                uint32_t Af[4][4], Bf[2][4];
                const int acolb = (ak0 + ks * 16 + lc * 8) * 2;
                #pragma unroll
                for (int mi = 0; mi < 4; mi++) {
                    int row = wm * 64 + mi * 16 + lr;
                    ldsm_x4(Af[mi], aA + row * 128 + (acolb ^ ((row & 7) << 4)));
                }
                const int brow = bk0 + ks * 16 + lr;
                #pragma unroll
                for (int g = 0; g < 2; g++) {
                    int colb = (wn * 32 + g * 16 + lc * 8) * 2;
                    ldsm_x4_t(Bf[g], aB + brow * 256 + (colb ^ ((brow & 7) << 4)));
                }
                #pragma unroll
                for (int mi = 0; mi < 4; mi++)
                    #pragma unroll
                    for (int nf = 0; nf < 4; nf++)
                        mma_bf16(d[mi][nf][0], d[mi][nf][1], d[mi][nf][2], d[mi][nf][3],
                                 Af[mi][0], Af[mi][1], Af[mi][2], Af[mi][3],
                                 Bf[nf >> 1][(nf & 1) * 2], Bf[nf >> 1][(nf & 1) * 2 + 1]);
            }
        }
        __syncthreads();
        if (f + NSTAGE < F_) issue_tile(f + NSTAGE);
        CP_COMMIT();
    }

    // epilogue: add w@b2 bias, store
    #pragma unroll
    for (int mi = 0; mi < 4; mi++) {
        int r0 = b0 + wm * 64 + mi * 16 + (lane >> 2);
        #pragma unroll
        for (int nf = 0; nf < 4; nf++) {
            int col = e0 + wn * 32 + nf * 8 + (lane & 3) * 2;
            float bx = __ldg(&g_wb2[col]), by = __ldg(&g_wb2[col + 1]);
            float2 v0 = make_float2(d[mi][nf][0] + bx, d[mi][nf][1] + by);
            float2 v1 = make_float2(d[mi][nf][2] + bx, d[mi][nf][3] + by);
            *(float2*)(out + (size_t)r0 * E_ + col)       = v0;
            *(float2*)(out + (size_t)(r0 + 8) * E_ + col) = v1;
        }
    }
}

// ---------------------------------------------------------------------------
extern "C" void kernel_launch(void* const* d_in, const int* in_sizes, int n_in,
                              void* d_out, int out_size) {
    const float* bf    = (const float*)d_in[0];   // batch_factors [B,F]
    const float* w_raw = (const float*)d_in[1];   // [F]
    const float* W1    = (const float*)d_in[2];   // [F,L,L]
    const float* b1    = (const float*)d_in[3];   // [F,L]
    const float* gamma = (const float*)d_in[4];   // [F,L]
    const float* beta  = (const float*)d_in[5];   // [F,L]
    const float* W2    = (const float*)d_in[6];   // [F,L,E]
    const float* b2    = (const float*)d_in[7];   // [F,E]
    float* out = (float*)d_out;

    prologue_kernel<<<1, 512>>>(w_raw, b2, out, out_size);
    prep_w2_kernel<<<F_, 512>>>(W2);

    size_t s1_smem = S1_FLOATS * sizeof(float);              // ~54KB
    cudaFuncSetAttribute(stage1_kernel,
                         cudaFuncAttributeMaxDynamicSharedMemorySize, (int)s1_smem);
    stage1_kernel<<<B_ / 128, 256, s1_smem>>>(bf, W1, b1, gamma, beta);

    size_t g_smem = NSTAGE * STAGE_BYTES;                    // 96KB
    cudaFuncSetAttribute(gemm_kernel,
                         cudaFuncAttributeMaxDynamicSharedMemorySize, (int)g_smem);
    dim3 grid(E_ / 128, B_ / 128);
    gemm_kernel<<<grid, 256, g_smem>>>(out);
}

// round 6
// speedup vs baseline: 3.0440x; 1.1065x over previous
#include <cuda_runtime.h>
#include <cuda_bf16.h>
#include <math.h>
#include <stdint.h>

#define B_ 65536
#define F_ 64
#define L_ 32
#define E_ 512

// ---------------- device scratch ----------------
__device__ float g_w[F_];
__device__ float g_wb2[E_];
// A: [b][f*64 + c]  c: 0..31 = bf16 hi of h*w, 32..63 = bf16 lo residual  (512MB)
__device__ __nv_bfloat16 g_A[(size_t)B_ * 4096];
// B: [f*64 + r][e]  r: 0..31 = bf16 hi of W2[f][r][e], 32..63 = lo        (4MB)
__device__ __nv_bfloat16 g_B[(size_t)F_ * 64 * E_];

// ---------------- asm helpers ----------------
__device__ __forceinline__ uint32_t smem_to_u32(const void* p) {
    uint32_t a;
    asm("{ .reg .u64 t; cvta.to.shared.u64 t, %1; cvt.u32.u64 %0, t; }" : "=r"(a) : "l"(p));
    return a;
}
__device__ __forceinline__ void cp_async16(uint32_t s, const void* g) {
    asm volatile("cp.async.cg.shared.global [%0], [%1], 16;" :: "r"(s), "l"(g));
}
#define CP_COMMIT() asm volatile("cp.async.commit_group;" ::: "memory")
#define CP_WAIT(n)  asm volatile("cp.async.wait_group %0;" :: "n"(n) : "memory")

__device__ __forceinline__ void ldsm_x4(uint32_t* r, uint32_t addr) {
    asm volatile("ldmatrix.sync.aligned.m8n8.x4.shared.b16 {%0,%1,%2,%3}, [%4];"
                 : "=r"(r[0]), "=r"(r[1]), "=r"(r[2]), "=r"(r[3]) : "r"(addr));
}
__device__ __forceinline__ void ldsm_x4_t(uint32_t* r, uint32_t addr) {
    asm volatile("ldmatrix.sync.aligned.m8n8.x4.trans.shared.b16 {%0,%1,%2,%3}, [%4];"
                 : "=r"(r[0]), "=r"(r[1]), "=r"(r[2]), "=r"(r[3]) : "r"(addr));
}
__device__ __forceinline__ void mma_bf16(float& d0, float& d1, float& d2, float& d3,
                                         uint32_t a0, uint32_t a1, uint32_t a2, uint32_t a3,
                                         uint32_t b0, uint32_t b1) {
    asm volatile("mma.sync.aligned.m16n8k16.row.col.f32.bf16.bf16.f32 "
                 "{%0,%1,%2,%3}, {%4,%5,%6,%7}, {%8,%9}, {%0,%1,%2,%3};"
                 : "+f"(d0), "+f"(d1), "+f"(d2), "+f"(d3)
                 : "r"(a0), "r"(a1), "r"(a2), "r"(a3), "r"(b0), "r"(b1));
}

// ---------------------------------------------------------------------------
// Prologue: softmax(w_raw) -> g_w (+ output tail), w @ b2 -> g_wb2
// ---------------------------------------------------------------------------
__global__ void prologue_kernel(const float* __restrict__ w_raw,
                                const float* __restrict__ b2,
                                float* __restrict__ d_out, int out_size) {
    __shared__ float sw[F_];
    int tid = threadIdx.x;
    if (tid < F_) sw[tid] = w_raw[tid];
    __syncthreads();
    float m = -INFINITY;
    for (int f = 0; f < F_; f++) m = fmaxf(m, sw[f]);
    float s = 0.f;
    for (int f = 0; f < F_; f++) s += expf(sw[f] - m);
    float inv = 1.f / s;
    __syncthreads();
    if (tid < F_) {
        float wv = expf(sw[tid] - m) * inv;
        sw[tid] = wv;
        g_w[tid] = wv;
        if (out_size >= B_ * E_ + F_) d_out[B_ * E_ + tid] = wv;
    }
    __syncthreads();
    for (int e = tid; e < E_; e += blockDim.x) {
        float acc = 0.f;
        for (int f = 0; f < F_; f++) acc = fmaf(sw[f], b2[f * E_ + e], acc);
        g_wb2[e] = acc;
    }
}

// ---------------------------------------------------------------------------
// Prep: W2[f][j][e] -> g_B hi rows (0..31) + lo rows (32..63)
// ---------------------------------------------------------------------------
__global__ void prep_w2_kernel(const float* __restrict__ W2) {
    int f = blockIdx.x;
    int e = threadIdx.x;
    const float* src = W2 + (size_t)f * L_ * E_ + e;
    __nv_bfloat16* dst = g_B + (size_t)(f * 64) * E_ + e;
    #pragma unroll
    for (int j = 0; j < 32; j++) {
        float a = src[(size_t)j * E_];
        __nv_bfloat16 h = __float2bfloat16(a);
        float r = a - __bfloat162float(h);
        dst[(size_t)j * E_]        = h;
        dst[(size_t)(32 + j) * E_] = __float2bfloat16(r);
    }
}

// ---------------------------------------------------------------------------
// Stage 1: enc -> W1 -> LN -> GELU -> *w[f]; emit bf16 hi/lo to g_A.
// grid = 512 (batch tiles of 128), block = 256.
// enc: split across all 256 threads (half: freqs 0..7 from anchor 0.1x,
// half: freqs 8..15 from anchor 25.6x; phases double exactly in fp32).
// ---------------------------------------------------------------------------
#define S1_SF    0                   // 128*65 floats
#define S1_W1    (128*65)            // 1024
#define S1_ENC   (S1_W1 + 1024)      // 128*36 floats, row-major [row][i], pad 36
#define S1_FLOATS (S1_ENC + 128*36)

__global__ void __launch_bounds__(256)
stage1_kernel(const float* __restrict__ bf,
              const float* __restrict__ W1,
              const float* __restrict__ b1,
              const float* __restrict__ gamma,
              const float* __restrict__ beta) {
    extern __shared__ float sm[];
    float* sF   = sm + S1_SF;
    float* sW1  = sm + S1_W1;
    float* sEnc = sm + S1_ENC;

    const int tid = threadIdx.x;
    const int b0 = blockIdx.x * 128;
    const int r1 = tid >> 1;             // h-compute: row 0..127
    const int jbase = (tid & 1) * 16;    // 0 or 16
    const int erow = tid & 127;          // enc: row
    const int ehi = tid >> 7;            // enc: 0 = freqs 0..7, 1 = freqs 8..15

    for (int idx = tid; idx < 128 * F_; idx += 256) {
        int r = idx >> 6, f = idx & 63;
        sF[r * 65 + f] = bf[(size_t)(b0 + r) * F_ + f];
    }
    __syncthreads();

    #pragma unroll 1
    for (int f = 0; f < F_; f++) {
        #pragma unroll
        for (int k = 0; k < 4; k++)
            sW1[tid + k * 256] = W1[f * 1024 + tid + k * 256];

        // ---- positional encoding: 1 sincosf + 7 exact-phase doublings ----
        {
            float x = sF[erow * 65 + f];
            float anchor = ehi ? (0.1f * 256.0f) : 0.1f;
            float s, c;
            sincosf(anchor * x, &s, &c);
            float sn[8], cs[8];
            sn[0] = s; cs[0] = c;
            #pragma unroll
            for (int k = 1; k < 8; k++) {
                float s2 = 2.f * s * c;
                float c2 = fmaf(-2.f * s, s, 1.f);
                s = s2; c = c2;
                sn[k] = s; cs[k] = c;
            }
            float* er = sEnc + erow * 36 + ehi * 8;
            *(float4*)(er)          = make_float4(sn[0], sn[1], sn[2], sn[3]);
            *(float4*)(er + 4)      = make_float4(sn[4], sn[5], sn[6], sn[7]);
            *(float4*)(er + 16)     = make_float4(cs[0], cs[1], cs[2], cs[3]);
            *(float4*)(er + 16 + 4) = make_float4(cs[4], cs[5], cs[6], cs[7]);
        }
        __syncthreads();

        // ---- h = enc@W1 + b1 -> LN -> GELU -> *w[f] -> g_A bf16 hi/lo ----
        {
            float h[16];
            {
                const float4* bv = (const float4*)(b1 + f * L_ + jbase);
                #pragma unroll
                for (int q = 0; q < 4; q++) {
                    float4 v = __ldg(&bv[q]);
                    h[q * 4 + 0] = v.x; h[q * 4 + 1] = v.y;
                    h[q * 4 + 2] = v.z; h[q * 4 + 3] = v.w;
                }
            }
            #pragma unroll
            for (int i = 0; i < 32; i += 4) {
                float4 e4 = *(const float4*)&sEnc[r1 * 36 + i];
                #pragma unroll
                for (int j = 0; j < 16; j++)
                    h[j] = fmaf(e4.x, sW1[(i + 0) * 32 + jbase + j], h[j]);
                #pragma unroll
                for (int j = 0; j < 16; j++)
                    h[j] = fmaf(e4.y, sW1[(i + 1) * 32 + jbase + j], h[j]);
                #pragma unroll
                for (int j = 0; j < 16; j++)
                    h[j] = fmaf(e4.z, sW1[(i + 2) * 32 + jbase + j], h[j]);
                #pragma unroll
                for (int j = 0; j < 16; j++)
                    h[j] = fmaf(e4.w, sW1[(i + 3) * 32 + jbase + j], h[j]);
            }
            float s1 = 0.f, s2 = 0.f;
            #pragma unroll
            for (int j = 0; j < 16; j++) { s1 += h[j]; s2 = fmaf(h[j], h[j], s2); }
            s1 += __shfl_xor_sync(0xffffffffu, s1, 1);
            s2 += __shfl_xor_sync(0xffffffffu, s2, 1);
            float mean = s1 * (1.f / 32.f);
            float var  = s2 * (1.f / 32.f) - mean * mean;
            float rstd = rsqrtf(var + 1e-5f);
            float wf = g_w[f];
            float a[16];
            {
                const float4* gv = (const float4*)(gamma + f * L_ + jbase);
                const float4* bv = (const float4*)(beta + f * L_ + jbase);
                #pragma unroll
                for (int q = 0; q < 4; q++) {
                    float4 gg = __ldg(&gv[q]);
                    float4 bb = __ldg(&bv[q]);
                    float gj[4] = {gg.x, gg.y, gg.z, gg.w};
                    float bj[4] = {bb.x, bb.y, bb.z, bb.w};
                    #pragma unroll
                    for (int r = 0; r < 4; r++) {
                        int j = q * 4 + r;
                        float hn = fmaf((h[j] - mean) * rstd, gj[r], bj[r]);
                        a[j] = 0.5f * hn * (1.f + erff(hn * 0.70710678118654752f)) * wf;
                    }
                }
            }
            uint32_t hu[8], lu[8];
            #pragma unroll
            for (int jj = 0; jj < 8; jj++) {
                unsigned short u0 = __bfloat16_as_ushort(__float2bfloat16(a[2 * jj]));
                unsigned short u1 = __bfloat16_as_ushort(__float2bfloat16(a[2 * jj + 1]));
                hu[jj] = (uint32_t)u0 | ((uint32_t)u1 << 16);
                float q0 = a[2 * jj]     - __bfloat162float(__ushort_as_bfloat16(u0));
                float q1 = a[2 * jj + 1] - __bfloat162float(__ushort_as_bfloat16(u1));
                lu[jj] = (uint32_t)__bfloat16_as_ushort(__float2bfloat16(q0)) |
                         ((uint32_t)__bfloat16_as_ushort(__float2bfloat16(q1)) << 16);
            }
            size_t base = (size_t)(b0 + r1) * 4096 + f * 64 + jbase;
            uint4* ph = (uint4*)(g_A + base);
            ph[0] = make_uint4(hu[0], hu[1], hu[2], hu[3]);
            ph[1] = make_uint4(hu[4], hu[5], hu[6], hu[7]);
            uint4* pl = (uint4*)(g_A + base + 32);
            pl[0] = make_uint4(lu[0], lu[1], lu[2], lu[3]);
            pl[1] = make_uint4(lu[4], lu[5], lu[6], lu[7]);
        }
        __syncthreads();   // protect sW1/sEnc before next f
    }
}

// ---------------------------------------------------------------------------
// Stage 2 GEMM: C = sum_f Ah.Bh + Ah.Bl + Al.Bh   (mma.sync bf16, fp32 accum)
// grid = (4 e-tiles, 512 b-tiles), block = 256 (8 warps, 64x32 each).
// 3-stage cp.async pipeline; per K-step loads Ah/Al/Bh/Bl once, 3 mma groups.
// ---------------------------------------------------------------------------
#define NSTAGE 3
#define STAGE_BYTES 32768

__global__ void __launch_bounds__(256, 2)
gemm_kernel(float* __restrict__ out) {
    extern __shared__ char smem[];
    const uint32_t sb = smem_to_u32(smem);
    const int tid = threadIdx.x, wid = tid >> 5, lane = tid & 31;
    const int wm = wid & 1, wn = wid >> 1;
    const int e0 = blockIdx.x * 128, b0 = blockIdx.y * 128;
    const int lr = lane & 15, lc = lane >> 4;

    float d[4][4][4];
    #pragma unroll
    for (int mi = 0; mi < 4; mi++)
        #pragma unroll
        for (int nf = 0; nf < 4; nf++)
            #pragma unroll
            for (int q = 0; q < 4; q++) d[mi][nf][q] = 0.f;

    auto issue_tile = [&](int f) {
        uint32_t s = sb + (f % NSTAGE) * STAGE_BYTES;
        const char* gA0 = (const char*)(g_A + (size_t)b0 * 4096 + f * 64);
        #pragma unroll
        for (int k = 0; k < 4; k++) {
            int c = tid + k * 256;           // 0..1023
            int r = c >> 3, off = (c & 7) * 16;
            cp_async16(s + r * 128 + (off ^ ((r & 7) << 4)),
                       gA0 + (size_t)r * 8192 + off);
        }
        const char* gB0 = (const char*)(g_B + (size_t)(f * 64) * E_ + e0);
        uint32_t sB = s + 16384;
        #pragma unroll
        for (int k = 0; k < 4; k++) {
            int c = tid + k * 256;           // 0..1023
            int kr = c >> 4, off = (c & 15) * 16;
            cp_async16(sB + kr * 256 + (off ^ ((kr & 7) << 4)),
                       gB0 + (size_t)kr * 1024 + off);
        }
    };

    issue_tile(0); CP_COMMIT();
    issue_tile(1); CP_COMMIT();
    issue_tile(2); CP_COMMIT();

    #pragma unroll 1
    for (int f = 0; f < F_; f++) {
        CP_WAIT(2);
        __syncthreads();
        const uint32_t aA = sb + (f % NSTAGE) * STAGE_BYTES;
        const uint32_t aB = aA + 16384;

        #pragma unroll
        for (int ks = 0; ks < 2; ks++) {
            uint32_t Ah[4][4], Al[4][4], Bh[2][4], Bl[2][4];

            // load Ah (hi cols), Bh (hi rows)
            const int acolh = (ks * 16 + lc * 8) * 2;
            #pragma unroll
            for (int mi = 0; mi < 4; mi++) {
                int row = wm * 64 + mi * 16 + lr;
                ldsm_x4(Ah[mi], aA + row * 128 + (acolh ^ ((row & 7) << 4)));
            }
            const int browh = ks * 16 + lr;
            #pragma unroll
            for (int g = 0; g < 2; g++) {
                int colb = (wn * 32 + g * 16 + lc * 8) * 2;
                ldsm_x4_t(Bh[g], aB + browh * 256 + (colb ^ ((browh & 7) << 4)));
            }
            // mma: Ah . Bh
            #pragma unroll
            for (int mi = 0; mi < 4; mi++)
                #pragma unroll
                for (int nf = 0; nf < 4; nf++)
                    mma_bf16(d[mi][nf][0], d[mi][nf][1], d[mi][nf][2], d[mi][nf][3],
                             Ah[mi][0], Ah[mi][1], Ah[mi][2], Ah[mi][3],
                             Bh[nf >> 1][(nf & 1) * 2], Bh[nf >> 1][(nf & 1) * 2 + 1]);

            // load Bl (lo rows); mma: Ah . Bl
            const int browl = 32 + ks * 16 + lr;
            #pragma unroll
            for (int g = 0; g < 2; g++) {
                int colb = (wn * 32 + g * 16 + lc * 8) * 2;
                ldsm_x4_t(Bl[g], aB + browl * 256 + (colb ^ ((browl & 7) << 4)));
            }
            #pragma unroll
            for (int mi = 0; mi < 4; mi++)
                #pragma unroll
                for (int nf = 0; nf < 4; nf++)
                    mma_bf16(d[mi][nf][0], d[mi][nf][1], d[mi][nf][2], d[mi][nf][3],
                             Ah[mi][0], Ah[mi][1], Ah[mi][2], Ah[mi][3],
                             Bl[nf >> 1][(nf & 1) * 2], Bl[nf >> 1][(nf & 1) * 2 + 1]);

            // load Al (lo cols); mma: Al . Bh
            const int acoll = (32 + ks * 16 + lc * 8) * 2;
            #pragma unroll
            for (int mi = 0; mi < 4; mi++) {
                int row = wm * 64 + mi * 16 + lr;
                ldsm_x4(Al[mi], aA + row * 128 + (acoll ^ ((row & 7) << 4)));
            }
            #pragma unroll
            for (int mi = 0; mi < 4; mi++)
                #pragma unroll
                for (int nf = 0; nf < 4; nf++)
                    mma_bf16(d[mi][nf][0], d[mi][nf][1], d[mi][nf][2], d[mi][nf][3],
                             Al[mi][0], Al[mi][1], Al[mi][2], Al[mi][3],
                             Bh[nf >> 1][(nf & 1) * 2], Bh[nf >> 1][(nf & 1) * 2 + 1]);
        }
        __syncthreads();
        if (f + NSTAGE < F_) issue_tile(f + NSTAGE);
        CP_COMMIT();
    }

    // epilogue: add w@b2 bias, store
    #pragma unroll
    for (int mi = 0; mi < 4; mi++) {
        int r0 = b0 + wm * 64 + mi * 16 + (lane >> 2);
        #pragma unroll
        for (int nf = 0; nf < 4; nf++) {
            int col = e0 + wn * 32 + nf * 8 + (lane & 3) * 2;
            float bx = __ldg(&g_wb2[col]), by = __ldg(&g_wb2[col + 1]);
            float2 v0 = make_float2(d[mi][nf][0] + bx, d[mi][nf][1] + by);
            float2 v1 = make_float2(d[mi][nf][2] + bx, d[mi][nf][3] + by);
            *(float2*)(out + (size_t)r0 * E_ + col)       = v0;
            *(float2*)(out + (size_t)(r0 + 8) * E_ + col) = v1;
        }
    }
}

// ---------------------------------------------------------------------------
extern "C" void kernel_launch(void* const* d_in, const int* in_sizes, int n_in,
                              void* d_out, int out_size) {
    const float* bf    = (const float*)d_in[0];   // batch_factors [B,F]
    const float* w_raw = (const float*)d_in[1];   // [F]
    const float* W1    = (const float*)d_in[2];   // [F,L,L]
    const float* b1    = (const float*)d_in[3];   // [F,L]
    const float* gamma = (const float*)d_in[4];   // [F,L]
    const float* beta  = (const float*)d_in[5];   // [F,L]
    const float* W2    = (const float*)d_in[6];   // [F,L,E]
    const float* b2    = (const float*)d_in[7];   // [F,E]
    float* out = (float*)d_out;

    prologue_kernel<<<1, 512>>>(w_raw, b2, out, out_size);
    prep_w2_kernel<<<F_, 512>>>(W2);

    size_t s1_smem = S1_FLOATS * sizeof(float);              // ~56KB
    cudaFuncSetAttribute(stage1_kernel,
                         cudaFuncAttributeMaxDynamicSharedMemorySize, (int)s1_smem);
    stage1_kernel<<<B_ / 128, 256, s1_smem>>>(bf, W1, b1, gamma, beta);

    size_t g_smem = NSTAGE * STAGE_BYTES;                    // 96KB
    cudaFuncSetAttribute(gemm_kernel,
                         cudaFuncAttributeMaxDynamicSharedMemorySize, (int)g_smem);
    dim3 grid(E_ / 128, B_ / 128);
    gemm_kernel<<<grid, 256, g_smem>>>(out);
}

// round 7
// speedup vs baseline: 3.8306x; 1.2584x over previous
#include <cuda_runtime.h>
#include <cuda_fp16.h>
#include <math.h>
#include <stdint.h>

#define B_ 65536
#define F_ 64
#define L_ 32
#define E_ 512

// ---------------- device scratch ----------------
__device__ float g_w[F_];
__device__ float g_wb2[E_];
// A: [b][f*64 + c]  c: 0..31 = fp16 hi of h*w, 32..63 = fp16 lo residual  (512MB)
__device__ __half g_A[(size_t)B_ * 4096];
// B: [f*32 + r][e]  fp16(W2[f][r][e])                                     (2MB)
__device__ __half g_B[(size_t)F_ * 32 * E_];

// ---------------- asm helpers ----------------
__device__ __forceinline__ uint32_t smem_to_u32(const void* p) {
    uint32_t a;
    asm("{ .reg .u64 t; cvta.to.shared.u64 t, %1; cvt.u32.u64 %0, t; }" : "=r"(a) : "l"(p));
    return a;
}
__device__ __forceinline__ void cp_async16(uint32_t s, const void* g) {
    asm volatile("cp.async.cg.shared.global [%0], [%1], 16;" :: "r"(s), "l"(g));
}
#define CP_COMMIT() asm volatile("cp.async.commit_group;" ::: "memory")
#define CP_WAIT(n)  asm volatile("cp.async.wait_group %0;" :: "n"(n) : "memory")

__device__ __forceinline__ void ldsm_x4(uint32_t* r, uint32_t addr) {
    asm volatile("ldmatrix.sync.aligned.m8n8.x4.shared.b16 {%0,%1,%2,%3}, [%4];"
                 : "=r"(r[0]), "=r"(r[1]), "=r"(r[2]), "=r"(r[3]) : "r"(addr));
}
__device__ __forceinline__ void ldsm_x4_t(uint32_t* r, uint32_t addr) {
    asm volatile("ldmatrix.sync.aligned.m8n8.x4.trans.shared.b16 {%0,%1,%2,%3}, [%4];"
                 : "=r"(r[0]), "=r"(r[1]), "=r"(r[2]), "=r"(r[3]) : "r"(addr));
}
__device__ __forceinline__ void mma_f16(float& d0, float& d1, float& d2, float& d3,
                                        uint32_t a0, uint32_t a1, uint32_t a2, uint32_t a3,
                                        uint32_t b0, uint32_t b1) {
    asm volatile("mma.sync.aligned.m16n8k16.row.col.f32.f16.f16.f32 "
                 "{%0,%1,%2,%3}, {%4,%5,%6,%7}, {%8,%9}, {%0,%1,%2,%3};"
                 : "+f"(d0), "+f"(d1), "+f"(d2), "+f"(d3)
                 : "r"(a0), "r"(a1), "r"(a2), "r"(a3), "r"(b0), "r"(b1));
}

// ---------------------------------------------------------------------------
// Prologue: softmax(w_raw) -> g_w (+ output tail), w @ b2 -> g_wb2
// ---------------------------------------------------------------------------
__global__ void prologue_kernel(const float* __restrict__ w_raw,
                                const float* __restrict__ b2,
                                float* __restrict__ d_out, int out_size) {
    __shared__ float sw[F_];
    int tid = threadIdx.x;
    if (tid < F_) sw[tid] = w_raw[tid];
    __syncthreads();
    float m = -INFINITY;
    for (int f = 0; f < F_; f++) m = fmaxf(m, sw[f]);
    float s = 0.f;
    for (int f = 0; f < F_; f++) s += expf(sw[f] - m);
    float inv = 1.f / s;
    __syncthreads();
    if (tid < F_) {
        float wv = expf(sw[tid] - m) * inv;
        sw[tid] = wv;
        g_w[tid] = wv;
        if (out_size >= B_ * E_ + F_) d_out[B_ * E_ + tid] = wv;
    }
    __syncthreads();
    for (int e = tid; e < E_; e += blockDim.x) {
        float acc = 0.f;
        for (int f = 0; f < F_; f++) acc = fmaf(sw[f], b2[f * E_ + e], acc);
        g_wb2[e] = acc;
    }
}

// ---------------------------------------------------------------------------
// Prep: W2[f][j][e] -> g_B fp16
// ---------------------------------------------------------------------------
__global__ void prep_w2_kernel(const float* __restrict__ W2) {
    int f = blockIdx.x;
    int e = threadIdx.x;
    const float* src = W2 + (size_t)f * L_ * E_ + e;
    __half* dst = g_B + (size_t)(f * 32) * E_ + e;
    #pragma unroll
    for (int j = 0; j < 32; j++)
        dst[(size_t)j * E_] = __float2half(src[(size_t)j * E_]);
}

// ---------------------------------------------------------------------------
// Stage 1: enc -> W1 -> LN -> GELU -> *w[f]; emit fp16 hi + fp16 residual.
// grid = 512 (batch tiles of 128), block = 256.
// ---------------------------------------------------------------------------
#define S1_SF    0                   // 128*65 floats
#define S1_W1    (128*65)            // 1024
#define S1_ENC   (S1_W1 + 1024)      // 128*36 floats, row-major [row][i]
#define S1_FLOATS (S1_ENC + 128*36)

__global__ void __launch_bounds__(256)
stage1_kernel(const float* __restrict__ bf,
              const float* __restrict__ W1,
              const float* __restrict__ b1,
              const float* __restrict__ gamma,
              const float* __restrict__ beta) {
    extern __shared__ float sm[];
    float* sF   = sm + S1_SF;
    float* sW1  = sm + S1_W1;
    float* sEnc = sm + S1_ENC;

    const int tid = threadIdx.x;
    const int b0 = blockIdx.x * 128;
    const int r1 = tid >> 1;             // h-compute: row 0..127
    const int jbase = (tid & 1) * 16;    // 0 or 16
    const int erow = tid & 127;          // enc: row
    const int ehi = tid >> 7;            // enc: 0 = freqs 0..7, 1 = freqs 8..15

    for (int idx = tid; idx < 128 * F_; idx += 256) {
        int r = idx >> 6, f = idx & 63;
        sF[r * 65 + f] = bf[(size_t)(b0 + r) * F_ + f];
    }
    __syncthreads();

    #pragma unroll 1
    for (int f = 0; f < F_; f++) {
        #pragma unroll
        for (int k = 0; k < 4; k++)
            sW1[tid + k * 256] = W1[f * 1024 + tid + k * 256];

        // ---- positional encoding: 1 sincosf + 7 exact-phase doublings ----
        {
            float x = sF[erow * 65 + f];
            float anchor = ehi ? (0.1f * 256.0f) : 0.1f;
            float s, c;
            sincosf(anchor * x, &s, &c);
            float sn[8], cs[8];
            sn[0] = s; cs[0] = c;
            #pragma unroll
            for (int k = 1; k < 8; k++) {
                float s2 = 2.f * s * c;
                float c2 = fmaf(-2.f * s, s, 1.f);
                s = s2; c = c2;
                sn[k] = s; cs[k] = c;
            }
            float* er = sEnc + erow * 36 + ehi * 8;
            *(float4*)(er)          = make_float4(sn[0], sn[1], sn[2], sn[3]);
            *(float4*)(er + 4)      = make_float4(sn[4], sn[5], sn[6], sn[7]);
            *(float4*)(er + 16)     = make_float4(cs[0], cs[1], cs[2], cs[3]);
            *(float4*)(er + 16 + 4) = make_float4(cs[4], cs[5], cs[6], cs[7]);
        }
        __syncthreads();

        // ---- h = enc@W1 + b1 -> LN -> GELU -> *w[f] -> g_A fp16 hi/lo ----
        {
            float h[16];
            {
                const float4* bv = (const float4*)(b1 + f * L_ + jbase);
                #pragma unroll
                for (int q = 0; q < 4; q++) {
                    float4 v = __ldg(&bv[q]);
                    h[q * 4 + 0] = v.x; h[q * 4 + 1] = v.y;
                    h[q * 4 + 2] = v.z; h[q * 4 + 3] = v.w;
                }
            }
            #pragma unroll
            for (int i = 0; i < 32; i += 4) {
                float4 e4 = *(const float4*)&sEnc[r1 * 36 + i];
                #pragma unroll
                for (int j = 0; j < 16; j++)
                    h[j] = fmaf(e4.x, sW1[(i + 0) * 32 + jbase + j], h[j]);
                #pragma unroll
                for (int j = 0; j < 16; j++)
                    h[j] = fmaf(e4.y, sW1[(i + 1) * 32 + jbase + j], h[j]);
                #pragma unroll
                for (int j = 0; j < 16; j++)
                    h[j] = fmaf(e4.z, sW1[(i + 2) * 32 + jbase + j], h[j]);
                #pragma unroll
                for (int j = 0; j < 16; j++)
                    h[j] = fmaf(e4.w, sW1[(i + 3) * 32 + jbase + j], h[j]);
            }
            float s1 = 0.f, s2 = 0.f;
            #pragma unroll
            for (int j = 0; j < 16; j++) { s1 += h[j]; s2 = fmaf(h[j], h[j], s2); }
            s1 += __shfl_xor_sync(0xffffffffu, s1, 1);
            s2 += __shfl_xor_sync(0xffffffffu, s2, 1);
            float mean = s1 * (1.f / 32.f);
            float var  = s2 * (1.f / 32.f) - mean * mean;
            float rstd = rsqrtf(var + 1e-5f);
            float wf = g_w[f];
            float a[16];
            {
                const float4* gv = (const float4*)(gamma + f * L_ + jbase);
                const float4* bv = (const float4*)(beta + f * L_ + jbase);
                #pragma unroll
                for (int q = 0; q < 4; q++) {
                    float4 gg = __ldg(&gv[q]);
                    float4 bb = __ldg(&bv[q]);
                    float gj[4] = {gg.x, gg.y, gg.z, gg.w};
                    float bj[4] = {bb.x, bb.y, bb.z, bb.w};
                    #pragma unroll
                    for (int r = 0; r < 4; r++) {
                        int j = q * 4 + r;
                        float hn = fmaf((h[j] - mean) * rstd, gj[r], bj[r]);
                        a[j] = 0.5f * hn * (1.f + erff(hn * 0.70710678118654752f)) * wf;
                    }
                }
            }
            uint32_t hu[8], lu[8];
            #pragma unroll
            for (int jj = 0; jj < 8; jj++) {
                __half t0 = __float2half(a[2 * jj]);
                __half t1 = __float2half(a[2 * jj + 1]);
                hu[jj] = (uint32_t)__half_as_ushort(t0) |
                         ((uint32_t)__half_as_ushort(t1) << 16);
                float q0 = a[2 * jj]     - __half2float(t0);
                float q1 = a[2 * jj + 1] - __half2float(t1);
                lu[jj] = (uint32_t)__half_as_ushort(__float2half(q0)) |
                         ((uint32_t)__half_as_ushort(__float2half(q1)) << 16);
            }
            size_t base = (size_t)(b0 + r1) * 4096 + f * 64 + jbase;
            uint4* ph = (uint4*)(g_A + base);
            ph[0] = make_uint4(hu[0], hu[1], hu[2], hu[3]);
            ph[1] = make_uint4(hu[4], hu[5], hu[6], hu[7]);
            uint4* pl = (uint4*)(g_A + base + 32);
            pl[0] = make_uint4(lu[0], lu[1], lu[2], lu[3]);
            pl[1] = make_uint4(lu[4], lu[5], lu[6], lu[7]);
        }
        __syncthreads();   // protect sW1/sEnc before next f
    }
}

// ---------------------------------------------------------------------------
// Stage 2 GEMM: C = sum_f Ah.B + Al.B   (mma.sync fp16, fp32 accum, 2-pass)
// grid = (4 e-tiles, 512 b-tiles), block = 256 (8 warps, 64x32 each).
// 3-stage cp.async pipeline; A tile 128x64 fp16 (16KB), B tile 32x128 (8KB).
// ---------------------------------------------------------------------------
#define NSTAGE 3
#define STAGE_BYTES 24576
#define B_OFF 16384

__global__ void __launch_bounds__(256, 2)
gemm_kernel(float* __restrict__ out) {
    extern __shared__ char smem[];
    const uint32_t sb = smem_to_u32(smem);
    const int tid = threadIdx.x, wid = tid >> 5, lane = tid & 31;
    const int wm = wid & 1, wn = wid >> 1;
    const int e0 = blockIdx.x * 128, b0 = blockIdx.y * 128;
    const int lr = lane & 15, lc = lane >> 4;

    float d[4][4][4];
    #pragma unroll
    for (int mi = 0; mi < 4; mi++)
        #pragma unroll
        for (int nf = 0; nf < 4; nf++)
            #pragma unroll
            for (int q = 0; q < 4; q++) d[mi][nf][q] = 0.f;

    auto issue_tile = [&](int f) {
        uint32_t s = sb + (f % NSTAGE) * STAGE_BYTES;
        const char* gA0 = (const char*)(g_A + (size_t)b0 * 4096 + f * 64);
        #pragma unroll
        for (int k = 0; k < 4; k++) {
            int c = tid + k * 256;           // 0..1023
            int r = c >> 3, off = (c & 7) * 16;
            cp_async16(s + r * 128 + (off ^ ((r & 7) << 4)),
                       gA0 + (size_t)r * 8192 + off);
        }
        const char* gB0 = (const char*)(g_B + (size_t)(f * 32) * E_ + e0);
        uint32_t sB = s + B_OFF;
        #pragma unroll
        for (int k = 0; k < 2; k++) {
            int c = tid + k * 256;           // 0..511
            int kr = c >> 4, off = (c & 15) * 16;
            cp_async16(sB + kr * 256 + (off ^ ((kr & 7) << 4)),
                       gB0 + (size_t)kr * 1024 + off);
        }
    };

    issue_tile(0); CP_COMMIT();
    issue_tile(1); CP_COMMIT();
    issue_tile(2); CP_COMMIT();

    #pragma unroll 1
    for (int f = 0; f < F_; f++) {
        CP_WAIT(2);
        __syncthreads();
        const uint32_t aA = sb + (f % NSTAGE) * STAGE_BYTES;
        const uint32_t aB = aA + B_OFF;

        #pragma unroll
        for (int ks = 0; ks < 2; ks++) {
            uint32_t Ah[4][4], Al[4][4], Bf[2][4];

            // load B (single fp16), Ah (hi cols)
            const int brow = ks * 16 + lr;
            #pragma unroll
            for (int g = 0; g < 2; g++) {
                int colb = (wn * 32 + g * 16 + lc * 8) * 2;
                ldsm_x4_t(Bf[g], aB + brow * 256 + (colb ^ ((brow & 7) << 4)));
            }
            const int acolh = (ks * 16 + lc * 8) * 2;
            #pragma unroll
            for (int mi = 0; mi < 4; mi++) {
                int row = wm * 64 + mi * 16 + lr;
                ldsm_x4(Ah[mi], aA + row * 128 + (acolh ^ ((row & 7) << 4)));
            }
            // mma: Ah . B
            #pragma unroll
            for (int mi = 0; mi < 4; mi++)
                #pragma unroll
                for (int nf = 0; nf < 4; nf++)
                    mma_f16(d[mi][nf][0], d[mi][nf][1], d[mi][nf][2], d[mi][nf][3],
                            Ah[mi][0], Ah[mi][1], Ah[mi][2], Ah[mi][3],
                            Bf[nf >> 1][(nf & 1) * 2], Bf[nf >> 1][(nf & 1) * 2 + 1]);

            // load Al (lo cols); mma: Al . B
            const int acoll = (32 + ks * 16 + lc * 8) * 2;
            #pragma unroll
            for (int mi = 0; mi < 4; mi++) {
                int row = wm * 64 + mi * 16 + lr;
                ldsm_x4(Al[mi], aA + row * 128 + (acoll ^ ((row & 7) << 4)));
            }
            #pragma unroll
            for (int mi = 0; mi < 4; mi++)
                #pragma unroll
                for (int nf = 0; nf < 4; nf++)
                    mma_f16(d[mi][nf][0], d[mi][nf][1], d[mi][nf][2], d[mi][nf][3],
                            Al[mi][0], Al[mi][1], Al[mi][2], Al[mi][3],
                            Bf[nf >> 1][(nf & 1) * 2], Bf[nf >> 1][(nf & 1) * 2 + 1]);
        }
        __syncthreads();
        if (f + NSTAGE < F_) issue_tile(f + NSTAGE);
        CP_COMMIT();
    }

    // epilogue: add w@b2 bias, store
    #pragma unroll
    for (int mi = 0; mi < 4; mi++) {
        int r0 = b0 + wm * 64 + mi * 16 + (lane >> 2);
        #pragma unroll
        for (int nf = 0; nf < 4; nf++) {
            int col = e0 + wn * 32 + nf * 8 + (lane & 3) * 2;
            float bx = __ldg(&g_wb2[col]), by = __ldg(&g_wb2[col + 1]);
            float2 v0 = make_float2(d[mi][nf][0] + bx, d[mi][nf][1] + by);
            float2 v1 = make_float2(d[mi][nf][2] + bx, d[mi][nf][3] + by);
            *(float2*)(out + (size_t)r0 * E_ + col)       = v0;
            *(float2*)(out + (size_t)(r0 + 8) * E_ + col) = v1;
        }
    }
}

// ---------------------------------------------------------------------------
extern "C" void kernel_launch(void* const* d_in, const int* in_sizes, int n_in,
                              void* d_out, int out_size) {
    const float* bf    = (const float*)d_in[0];   // batch_factors [B,F]
    const float* w_raw = (const float*)d_in[1];   // [F]
    const float* W1    = (const float*)d_in[2];   // [F,L,L]
    const float* b1    = (const float*)d_in[3];   // [F,L]
    const float* gamma = (const float*)d_in[4];   // [F,L]
    const float* beta  = (const float*)d_in[5];   // [F,L]
    const float* W2    = (const float*)d_in[6];   // [F,L,E]
    const float* b2    = (const float*)d_in[7];   // [F,E]
    float* out = (float*)d_out;

    prologue_kernel<<<1, 512>>>(w_raw, b2, out, out_size);
    prep_w2_kernel<<<F_, 512>>>(W2);

    size_t s1_smem = S1_FLOATS * sizeof(float);              // ~56KB
    cudaFuncSetAttribute(stage1_kernel,
                         cudaFuncAttributeMaxDynamicSharedMemorySize, (int)s1_smem);
    stage1_kernel<<<B_ / 128, 256, s1_smem>>>(bf, W1, b1, gamma, beta);

    size_t g_smem = NSTAGE * STAGE_BYTES;                    // 72KB
    cudaFuncSetAttribute(gemm_kernel,
                         cudaFuncAttributeMaxDynamicSharedMemorySize, (int)g_smem);
    dim3 grid(E_ / 128, B_ / 128);
    gemm_kernel<<<grid, 256, g_smem>>>(out);
}

// round 8
// speedup vs baseline: 3.8592x; 1.0075x over previous
#include <cuda_runtime.h>
#include <cuda_fp16.h>
#include <math.h>
#include <stdint.h>

#define B_ 65536
#define F_ 64
#define L_ 32
#define E_ 512

// ---------------- device scratch ----------------
__device__ float g_w[F_];
__device__ float g_wb2[E_];
// A: [b][f*64 + c]  c: 0..31 = fp16 hi of h*w, 32..63 = fp16 lo residual  (512MB)
__device__ __half g_A[(size_t)B_ * 4096];
// B: [f*32 + r][e]  fp16(W2[f][r][e])                                     (2MB)
__device__ __half g_B[(size_t)F_ * 32 * E_];

// ---------------- asm helpers ----------------
__device__ __forceinline__ uint32_t smem_to_u32(const void* p) {
    uint32_t a;
    asm("{ .reg .u64 t; cvta.to.shared.u64 t, %1; cvt.u32.u64 %0, t; }" : "=r"(a) : "l"(p));
    return a;
}
__device__ __forceinline__ void cp_async16(uint32_t s, const void* g) {
    asm volatile("cp.async.cg.shared.global [%0], [%1], 16;" :: "r"(s), "l"(g));
}
#define CP_COMMIT() asm volatile("cp.async.commit_group;" ::: "memory")
#define CP_WAIT(n)  asm volatile("cp.async.wait_group %0;" :: "n"(n) : "memory")

__device__ __forceinline__ void ldsm_x4(uint32_t* r, uint32_t addr) {
    asm volatile("ldmatrix.sync.aligned.m8n8.x4.shared.b16 {%0,%1,%2,%3}, [%4];"
                 : "=r"(r[0]), "=r"(r[1]), "=r"(r[2]), "=r"(r[3]) : "r"(addr));
}
__device__ __forceinline__ void ldsm_x4_t(uint32_t* r, uint32_t addr) {
    asm volatile("ldmatrix.sync.aligned.m8n8.x4.trans.shared.b16 {%0,%1,%2,%3}, [%4];"
                 : "=r"(r[0]), "=r"(r[1]), "=r"(r[2]), "=r"(r[3]) : "r"(addr));
}
__device__ __forceinline__ void mma_f16(float& d0, float& d1, float& d2, float& d3,
                                        uint32_t a0, uint32_t a1, uint32_t a2, uint32_t a3,
                                        uint32_t b0, uint32_t b1) {
    asm volatile("mma.sync.aligned.m16n8k16.row.col.f32.f16.f16.f32 "
                 "{%0,%1,%2,%3}, {%4,%5,%6,%7}, {%8,%9}, {%0,%1,%2,%3};"
                 : "+f"(d0), "+f"(d1), "+f"(d2), "+f"(d3)
                 : "r"(a0), "r"(a1), "r"(a2), "r"(a3), "r"(b0), "r"(b1));
}

// ---------------------------------------------------------------------------
// Prologue: softmax(w_raw) -> g_w (+ output tail), w @ b2 -> g_wb2
// ---------------------------------------------------------------------------
__global__ void prologue_kernel(const float* __restrict__ w_raw,
                                const float* __restrict__ b2,
                                float* __restrict__ d_out, int out_size) {
    __shared__ float sw[F_];
    int tid = threadIdx.x;
    if (tid < F_) sw[tid] = w_raw[tid];
    __syncthreads();
    float m = -INFINITY;
    for (int f = 0; f < F_; f++) m = fmaxf(m, sw[f]);
    float s = 0.f;
    for (int f = 0; f < F_; f++) s += expf(sw[f] - m);
    float inv = 1.f / s;
    __syncthreads();
    if (tid < F_) {
        float wv = expf(sw[tid] - m) * inv;
        sw[tid] = wv;
        g_w[tid] = wv;
        if (out_size >= B_ * E_ + F_) d_out[B_ * E_ + tid] = wv;
    }
    __syncthreads();
    for (int e = tid; e < E_; e += blockDim.x) {
        float acc = 0.f;
        for (int f = 0; f < F_; f++) acc = fmaf(sw[f], b2[f * E_ + e], acc);
        g_wb2[e] = acc;
    }
}

// ---------------------------------------------------------------------------
// Prep: W2[f][j][e] -> g_B fp16
// ---------------------------------------------------------------------------
__global__ void prep_w2_kernel(const float* __restrict__ W2) {
    int f = blockIdx.x;
    int e = threadIdx.x;
    const float* src = W2 + (size_t)f * L_ * E_ + e;
    __half* dst = g_B + (size_t)(f * 32) * E_ + e;
    #pragma unroll
    for (int j = 0; j < 32; j++)
        dst[(size_t)j * E_] = __float2half(src[(size_t)j * E_]);
}

// ---------------------------------------------------------------------------
// Stage 1: enc -> W1 -> LN -> GELU -> *w[f]; emit fp16 hi + fp16 residual.
// grid = 512 (batch tiles of 128), block = 256.
// W1 double-buffered via cp.async; b1/gamma/beta resident in smem.
// ---------------------------------------------------------------------------
#define S1_W1    0                    // 2 x 1024 floats (double buffer)
#define S1_ENC   2048                 // 128*36 floats
#define S1_B1    (S1_ENC + 128*36)    // 2048
#define S1_G     (S1_B1 + 2048)      // 2048
#define S1_BT    (S1_G + 2048)       // 2048
#define S1_FLOATS (S1_BT + 2048)     // 12800 floats = 51.2KB

__global__ void __launch_bounds__(256)
stage1_kernel(const float* __restrict__ bf,
              const float* __restrict__ W1,
              const float* __restrict__ b1,
              const float* __restrict__ gamma,
              const float* __restrict__ beta) {
    extern __shared__ float sm[];
    float* sW1  = sm + S1_W1;
    float* sEnc = sm + S1_ENC;
    float* sB1  = sm + S1_B1;
    float* sG   = sm + S1_G;
    float* sBt  = sm + S1_BT;
    const uint32_t sW1u = smem_to_u32(sm + S1_W1);

    const int tid = threadIdx.x;
    const int b0 = blockIdx.x * 128;
    const int r1 = tid >> 1;             // h-compute: row 0..127
    const int jbase = (tid & 1) * 16;    // 0 or 16
    const int erow = tid & 127;          // enc: row
    const int ehi = tid >> 7;            // enc: 0 = freqs 0..7, 1 = freqs 8..15

    // preload b1/gamma/beta (2048 floats each) + W1[0] via cp.async
    {
        const float4* s1 = (const float4*)b1;
        const float4* s2 = (const float4*)gamma;
        const float4* s3 = (const float4*)beta;
        float4* d1 = (float4*)sB1;
        float4* d2 = (float4*)sG;
        float4* d3 = (float4*)sBt;
        #pragma unroll
        for (int i = tid; i < 512; i += 256) {
            d1[i] = __ldg(&s1[i]);
            d2[i] = __ldg(&s2[i]);
            d3[i] = __ldg(&s3[i]);
        }
        cp_async16(sW1u + tid * 16, W1 + tid * 4);   // W1[0] -> buf 0
        CP_COMMIT();
    }
    __syncthreads();

    #pragma unroll 1
    for (int f = 0; f < F_; f++) {
        // prefetch W1[f+1] into the other buffer
        if (f + 1 < F_)
            cp_async16(sW1u + ((f + 1) & 1) * 4096 + tid * 16,
                       W1 + (f + 1) * 1024 + tid * 4);
        CP_COMMIT();

        // ---- positional encoding: 1 sincosf + 7 exact-phase doublings ----
        {
            float x = __ldg(&bf[(size_t)(b0 + erow) * F_ + f]);
            float anchor = ehi ? (0.1f * 256.0f) : 0.1f;
            float s, c;
            sincosf(anchor * x, &s, &c);
            float sn[8], cs[8];
            sn[0] = s; cs[0] = c;
            #pragma unroll
            for (int k = 1; k < 8; k++) {
                float s2 = 2.f * s * c;
                float c2 = fmaf(-2.f * s, s, 1.f);
                s = s2; c = c2;
                sn[k] = s; cs[k] = c;
            }
            float* er = sEnc + erow * 36 + ehi * 8;
            *(float4*)(er)          = make_float4(sn[0], sn[1], sn[2], sn[3]);
            *(float4*)(er + 4)      = make_float4(sn[4], sn[5], sn[6], sn[7]);
            *(float4*)(er + 16)     = make_float4(cs[0], cs[1], cs[2], cs[3]);
            *(float4*)(er + 16 + 4) = make_float4(cs[4], cs[5], cs[6], cs[7]);
        }
        CP_WAIT(1);         // W1[f] landed (group f); group f+1 may be in flight
        __syncthreads();    // sEnc ready + W1[f] visible to all

        // ---- h = enc@W1 + b1 -> LN -> GELU -> *w[f] -> g_A fp16 hi/lo ----
        {
            const float* w1f = sW1 + (f & 1) * 1024;
            float h[16];
            #pragma unroll
            for (int j = 0; j < 16; j++) h[j] = sB1[f * 32 + jbase + j];
            #pragma unroll
            for (int i = 0; i < 32; i += 4) {
                float4 e4 = *(const float4*)&sEnc[r1 * 36 + i];
                #pragma unroll
                for (int j = 0; j < 16; j++)
                    h[j] = fmaf(e4.x, w1f[(i + 0) * 32 + jbase + j], h[j]);
                #pragma unroll
                for (int j = 0; j < 16; j++)
                    h[j] = fmaf(e4.y, w1f[(i + 1) * 32 + jbase + j], h[j]);
                #pragma unroll
                for (int j = 0; j < 16; j++)
                    h[j] = fmaf(e4.z, w1f[(i + 2) * 32 + jbase + j], h[j]);
                #pragma unroll
                for (int j = 0; j < 16; j++)
                    h[j] = fmaf(e4.w, w1f[(i + 3) * 32 + jbase + j], h[j]);
            }
            float s1 = 0.f, s2 = 0.f;
            #pragma unroll
            for (int j = 0; j < 16; j++) { s1 += h[j]; s2 = fmaf(h[j], h[j], s2); }
            s1 += __shfl_xor_sync(0xffffffffu, s1, 1);
            s2 += __shfl_xor_sync(0xffffffffu, s2, 1);
            float mean = s1 * (1.f / 32.f);
            float var  = s2 * (1.f / 32.f) - mean * mean;
            float rstd = rsqrtf(var + 1e-5f);
            float wf = g_w[f];
            float a[16];
            #pragma unroll
            for (int j = 0; j < 16; j++) {
                float hn = fmaf((h[j] - mean) * rstd, sG[f * 32 + jbase + j],
                                sBt[f * 32 + jbase + j]);
                a[j] = 0.5f * hn * (1.f + erff(hn * 0.70710678118654752f)) * wf;
            }
            uint32_t hu[8], lu[8];
            #pragma unroll
            for (int jj = 0; jj < 8; jj++) {
                __half t0 = __float2half(a[2 * jj]);
                __half t1 = __float2half(a[2 * jj + 1]);
                hu[jj] = (uint32_t)__half_as_ushort(t0) |
                         ((uint32_t)__half_as_ushort(t1) << 16);
                float q0 = a[2 * jj]     - __half2float(t0);
                float q1 = a[2 * jj + 1] - __half2float(t1);
                lu[jj] = (uint32_t)__half_as_ushort(__float2half(q0)) |
                         ((uint32_t)__half_as_ushort(__float2half(q1)) << 16);
            }
            size_t base = (size_t)(b0 + r1) * 4096 + f * 64 + jbase;
            uint4* ph = (uint4*)(g_A + base);
            ph[0] = make_uint4(hu[0], hu[1], hu[2], hu[3]);
            ph[1] = make_uint4(hu[4], hu[5], hu[6], hu[7]);
            uint4* pl = (uint4*)(g_A + base + 32);
            pl[0] = make_uint4(lu[0], lu[1], lu[2], lu[3]);
            pl[1] = make_uint4(lu[4], lu[5], lu[6], lu[7]);
        }
        __syncthreads();   // protect sEnc before next f
    }
}

// ---------------------------------------------------------------------------
// Stage 2 GEMM: C = sum_f Ah.B + Al.B   (mma.sync fp16, fp32 accum, 2-pass)
// grid = (4 e-tiles, 512 b-tiles), block = 256 (8 warps, 64x32 each).
// 3-stage cp.async pipeline; A tile 128x64 fp16 (16KB), B tile 32x128 (8KB).
// ---------------------------------------------------------------------------
#define NSTAGE 3
#define STAGE_BYTES 24576
#define B_OFF 16384

__global__ void __launch_bounds__(256, 2)
gemm_kernel(float* __restrict__ out) {
    extern __shared__ char smem[];
    const uint32_t sb = smem_to_u32(smem);
    const int tid = threadIdx.x, wid = tid >> 5, lane = tid & 31;
    const int wm = wid & 1, wn = wid >> 1;
    const int e0 = blockIdx.x * 128, b0 = blockIdx.y * 128;
    const int lr = lane & 15, lc = lane >> 4;

    float d[4][4][4];
    #pragma unroll
    for (int mi = 0; mi < 4; mi++)
        #pragma unroll
        for (int nf = 0; nf < 4; nf++)
            #pragma unroll
            for (int q = 0; q < 4; q++) d[mi][nf][q] = 0.f;

    auto issue_tile = [&](int f) {
        uint32_t s = sb + (f % NSTAGE) * STAGE_BYTES;
        const char* gA0 = (const char*)(g_A + (size_t)b0 * 4096 + f * 64);
        #pragma unroll
        for (int k = 0; k < 4; k++) {
            int c = tid + k * 256;           // 0..1023
            int r = c >> 3, off = (c & 7) * 16;
            cp_async16(s + r * 128 + (off ^ ((r & 7) << 4)),
                       gA0 + (size_t)r * 8192 + off);
        }
        const char* gB0 = (const char*)(g_B + (size_t)(f * 32) * E_ + e0);
        uint32_t sB = s + B_OFF;
        #pragma unroll
        for (int k = 0; k < 2; k++) {
            int c = tid + k * 256;           // 0..511
            int kr = c >> 4, off = (c & 15) * 16;
            cp_async16(sB + kr * 256 + (off ^ ((kr & 7) << 4)),
                       gB0 + (size_t)kr * 1024 + off);
        }
    };

    issue_tile(0); CP_COMMIT();
    issue_tile(1); CP_COMMIT();
    issue_tile(2); CP_COMMIT();

    #pragma unroll 1
    for (int f = 0; f < F_; f++) {
        CP_WAIT(2);
        __syncthreads();
        const uint32_t aA = sb + (f % NSTAGE) * STAGE_BYTES;
        const uint32_t aB = aA + B_OFF;

        #pragma unroll
        for (int ks = 0; ks < 2; ks++) {
            uint32_t Ah[4][4], Al[4][4], Bf[2][4];

            // load B (single fp16), Ah (hi cols)
            const int brow = ks * 16 + lr;
            #pragma unroll
            for (int g = 0; g < 2; g++) {
                int colb = (wn * 32 + g * 16 + lc * 8) * 2;
                ldsm_x4_t(Bf[g], aB + brow * 256 + (colb ^ ((brow & 7) << 4)));
            }
            const int acolh = (ks * 16 + lc * 8) * 2;
            #pragma unroll
            for (int mi = 0; mi < 4; mi++) {
                int row = wm * 64 + mi * 16 + lr;
                ldsm_x4(Ah[mi], aA + row * 128 + (acolh ^ ((row & 7) << 4)));
            }
            // mma: Ah . B
            #pragma unroll
            for (int mi = 0; mi < 4; mi++)
                #pragma unroll
                for (int nf = 0; nf < 4; nf++)
                    mma_f16(d[mi][nf][0], d[mi][nf][1], d[mi][nf][2], d[mi][nf][3],
                            Ah[mi][0], Ah[mi][1], Ah[mi][2], Ah[mi][3],
                            Bf[nf >> 1][(nf & 1) * 2], Bf[nf >> 1][(nf & 1) * 2 + 1]);

            // load Al (lo cols); mma: Al . B
            const int acoll = (32 + ks * 16 + lc * 8) * 2;
            #pragma unroll
            for (int mi = 0; mi < 4; mi++) {
                int row = wm * 64 + mi * 16 + lr;
                ldsm_x4(Al[mi], aA + row * 128 + (acoll ^ ((row & 7) << 4)));
            }
            #pragma unroll
            for (int mi = 0; mi < 4; mi++)
                #pragma unroll
                for (int nf = 0; nf < 4; nf++)
                    mma_f16(d[mi][nf][0], d[mi][nf][1], d[mi][nf][2], d[mi][nf][3],
                            Al[mi][0], Al[mi][1], Al[mi][2], Al[mi][3],
                            Bf[nf >> 1][(nf & 1) * 2], Bf[nf >> 1][(nf & 1) * 2 + 1]);
        }
        __syncthreads();
        if (f + NSTAGE < F_) issue_tile(f + NSTAGE);
        CP_COMMIT();
    }

    // epilogue: add w@b2 bias, store
    #pragma unroll
    for (int mi = 0; mi < 4; mi++) {
        int r0 = b0 + wm * 64 + mi * 16 + (lane >> 2);
        #pragma unroll
        for (int nf = 0; nf < 4; nf++) {
            int col = e0 + wn * 32 + nf * 8 + (lane & 3) * 2;
            float bx = __ldg(&g_wb2[col]), by = __ldg(&g_wb2[col + 1]);
            float2 v0 = make_float2(d[mi][nf][0] + bx, d[mi][nf][1] + by);
            float2 v1 = make_float2(d[mi][nf][2] + bx, d[mi][nf][3] + by);
            *(float2*)(out + (size_t)r0 * E_ + col)       = v0;
            *(float2*)(out + (size_t)(r0 + 8) * E_ + col) = v1;
        }
    }
}

// ---------------------------------------------------------------------------
extern "C" void kernel_launch(void* const* d_in, const int* in_sizes, int n_in,
                              void* d_out, int out_size) {
    const float* bf    = (const float*)d_in[0];   // batch_factors [B,F]
    const float* w_raw = (const float*)d_in[1];   // [F]
    const float* W1    = (const float*)d_in[2];   // [F,L,L]
    const float* b1    = (const float*)d_in[3];   // [F,L]
    const float* gamma = (const float*)d_in[4];   // [F,L]
    const float* beta  = (const float*)d_in[5];   // [F,L]
    const float* W2    = (const float*)d_in[6];   // [F,L,E]
    const float* b2    = (const float*)d_in[7];   // [F,E]
    float* out = (float*)d_out;

    prologue_kernel<<<1, 512>>>(w_raw, b2, out, out_size);
    prep_w2_kernel<<<F_, 512>>>(W2);

    size_t s1_smem = S1_FLOATS * sizeof(float);              // 51.2KB
    cudaFuncSetAttribute(stage1_kernel,
                         cudaFuncAttributeMaxDynamicSharedMemorySize, (int)s1_smem);
    stage1_kernel<<<B_ / 128, 256, s1_smem>>>(bf, W1, b1, gamma, beta);

    size_t g_smem = NSTAGE * STAGE_BYTES;                    // 72KB
    cudaFuncSetAttribute(gemm_kernel,
                         cudaFuncAttributeMaxDynamicSharedMemorySize, (int)g_smem);
    dim3 grid(E_ / 128, B_ / 128);
    gemm_kernel<<<grid, 256, g_smem>>>(out);
}

// round 9
// speedup vs baseline: 4.7532x; 1.2317x over previous
#include <cuda_runtime.h>
#include <cuda_fp16.h>
#include <math.h>
#include <stdint.h>

#define B_ 65536
#define F_ 64
#define L_ 32
#define E_ 512

// ---------------- device scratch ----------------
__device__ float g_w[F_];
__device__ float g_wb2[E_];
// A: [b][f*32 + j]  fp16(h*w)                                             (256MB)
__device__ __half g_A[(size_t)B_ * 2048];
// B: [f*32 + r][e]  fp16(W2[f][r][e])                                     (2MB)
__device__ __half g_B[(size_t)F_ * 32 * E_];

// ---------------- asm helpers ----------------
__device__ __forceinline__ uint32_t smem_to_u32(const void* p) {
    uint32_t a;
    asm("{ .reg .u64 t; cvta.to.shared.u64 t, %1; cvt.u32.u64 %0, t; }" : "=r"(a) : "l"(p));
    return a;
}
__device__ __forceinline__ void cp_async16(uint32_t s, const void* g) {
    asm volatile("cp.async.cg.shared.global [%0], [%1], 16;" :: "r"(s), "l"(g));
}
#define CP_COMMIT() asm volatile("cp.async.commit_group;" ::: "memory")
#define CP_WAIT(n)  asm volatile("cp.async.wait_group %0;" :: "n"(n) : "memory")

__device__ __forceinline__ void ldsm_x4(uint32_t* r, uint32_t addr) {
    asm volatile("ldmatrix.sync.aligned.m8n8.x4.shared.b16 {%0,%1,%2,%3}, [%4];"
                 : "=r"(r[0]), "=r"(r[1]), "=r"(r[2]), "=r"(r[3]) : "r"(addr));
}
__device__ __forceinline__ void ldsm_x4_t(uint32_t* r, uint32_t addr) {
    asm volatile("ldmatrix.sync.aligned.m8n8.x4.trans.shared.b16 {%0,%1,%2,%3}, [%4];"
                 : "=r"(r[0]), "=r"(r[1]), "=r"(r[2]), "=r"(r[3]) : "r"(addr));
}
__device__ __forceinline__ void mma_f16(float& d0, float& d1, float& d2, float& d3,
                                        uint32_t a0, uint32_t a1, uint32_t a2, uint32_t a3,
                                        uint32_t b0, uint32_t b1) {
    asm volatile("mma.sync.aligned.m16n8k16.row.col.f32.f16.f16.f32 "
                 "{%0,%1,%2,%3}, {%4,%5,%6,%7}, {%8,%9}, {%0,%1,%2,%3};"
                 : "+f"(d0), "+f"(d1), "+f"(d2), "+f"(d3)
                 : "r"(a0), "r"(a1), "r"(a2), "r"(a3), "r"(b0), "r"(b1));
}

// ---------------------------------------------------------------------------
// Prologue: softmax(w_raw) -> g_w (+ output tail), w @ b2 -> g_wb2
// ---------------------------------------------------------------------------
__global__ void prologue_kernel(const float* __restrict__ w_raw,
                                const float* __restrict__ b2,
                                float* __restrict__ d_out, int out_size) {
    __shared__ float sw[F_];
    int tid = threadIdx.x;
    if (tid < F_) sw[tid] = w_raw[tid];
    __syncthreads();
    float m = -INFINITY;
    for (int f = 0; f < F_; f++) m = fmaxf(m, sw[f]);
    float s = 0.f;
    for (int f = 0; f < F_; f++) s += expf(sw[f] - m);
    float inv = 1.f / s;
    __syncthreads();
    if (tid < F_) {
        float wv = expf(sw[tid] - m) * inv;
        sw[tid] = wv;
        g_w[tid] = wv;
        if (out_size >= B_ * E_ + F_) d_out[B_ * E_ + tid] = wv;
    }
    __syncthreads();
    for (int e = tid; e < E_; e += blockDim.x) {
        float acc = 0.f;
        for (int f = 0; f < F_; f++) acc = fmaf(sw[f], b2[f * E_ + e], acc);
        g_wb2[e] = acc;
    }
}

// ---------------------------------------------------------------------------
// Prep: W2[f][j][e] -> g_B fp16
// ---------------------------------------------------------------------------
__global__ void prep_w2_kernel(const float* __restrict__ W2) {
    int f = blockIdx.x;
    int e = threadIdx.x;
    const float* src = W2 + (size_t)f * L_ * E_ + e;
    __half* dst = g_B + (size_t)(f * 32) * E_ + e;
    #pragma unroll
    for (int j = 0; j < 32; j++)
        dst[(size_t)j * E_] = __float2half(src[(size_t)j * E_]);
}

// ---------------------------------------------------------------------------
// Stage 1: enc -> W1 -> LN -> GELU -> *w[f]; emit single fp16 to g_A.
// grid = 512 (batch tiles of 128), block = 256.
// W1 double-buffered via cp.async; b1/gamma/beta resident in smem.
// ---------------------------------------------------------------------------
#define S1_W1    0                    // 2 x 1024 floats (double buffer)
#define S1_ENC   2048                 // 128*36 floats
#define S1_B1    (S1_ENC + 128*36)    // 2048
#define S1_G     (S1_B1 + 2048)      // 2048
#define S1_BT    (S1_G + 2048)       // 2048
#define S1_FLOATS (S1_BT + 2048)     // 12800 floats = 51.2KB

__global__ void __launch_bounds__(256)
stage1_kernel(const float* __restrict__ bf,
              const float* __restrict__ W1,
              const float* __restrict__ b1,
              const float* __restrict__ gamma,
              const float* __restrict__ beta) {
    extern __shared__ float sm[];
    float* sW1  = sm + S1_W1;
    float* sEnc = sm + S1_ENC;
    float* sB1  = sm + S1_B1;
    float* sG   = sm + S1_G;
    float* sBt  = sm + S1_BT;
    const uint32_t sW1u = smem_to_u32(sm + S1_W1);

    const int tid = threadIdx.x;
    const int b0 = blockIdx.x * 128;
    const int r1 = tid >> 1;             // h-compute: row 0..127
    const int jbase = (tid & 1) * 16;    // 0 or 16
    const int erow = tid & 127;          // enc: row
    const int ehi = tid >> 7;            // enc: 0 = freqs 0..7, 1 = freqs 8..15

    // preload b1/gamma/beta (2048 floats each) + W1[0] via cp.async
    {
        const float4* s1 = (const float4*)b1;
        const float4* s2 = (const float4*)gamma;
        const float4* s3 = (const float4*)beta;
        float4* d1 = (float4*)sB1;
        float4* d2 = (float4*)sG;
        float4* d3 = (float4*)sBt;
        #pragma unroll
        for (int i = tid; i < 512; i += 256) {
            d1[i] = __ldg(&s1[i]);
            d2[i] = __ldg(&s2[i]);
            d3[i] = __ldg(&s3[i]);
        }
        cp_async16(sW1u + tid * 16, W1 + tid * 4);   // W1[0] -> buf 0
        CP_COMMIT();
    }
    __syncthreads();

    #pragma unroll 1
    for (int f = 0; f < F_; f++) {
        // prefetch W1[f+1] into the other buffer
        if (f + 1 < F_)
            cp_async16(sW1u + ((f + 1) & 1) * 4096 + tid * 16,
                       W1 + (f + 1) * 1024 + tid * 4);
        CP_COMMIT();

        // ---- positional encoding: 1 sincosf + 7 exact-phase doublings ----
        {
            float x = __ldg(&bf[(size_t)(b0 + erow) * F_ + f]);
            float anchor = ehi ? (0.1f * 256.0f) : 0.1f;
            float s, c;
            sincosf(anchor * x, &s, &c);
            float sn[8], cs[8];
            sn[0] = s; cs[0] = c;
            #pragma unroll
            for (int k = 1; k < 8; k++) {
                float s2 = 2.f * s * c;
                float c2 = fmaf(-2.f * s, s, 1.f);
                s = s2; c = c2;
                sn[k] = s; cs[k] = c;
            }
            float* er = sEnc + erow * 36 + ehi * 8;
            *(float4*)(er)          = make_float4(sn[0], sn[1], sn[2], sn[3]);
            *(float4*)(er + 4)      = make_float4(sn[4], sn[5], sn[6], sn[7]);
            *(float4*)(er + 16)     = make_float4(cs[0], cs[1], cs[2], cs[3]);
            *(float4*)(er + 16 + 4) = make_float4(cs[4], cs[5], cs[6], cs[7]);
        }
        CP_WAIT(1);         // W1[f] landed (group f); group f+1 may be in flight
        __syncthreads();    // sEnc ready + W1[f] visible to all

        // ---- h = enc@W1 + b1 -> LN -> GELU -> *w[f] -> g_A fp16 ----
        {
            const float* w1f = sW1 + (f & 1) * 1024;
            float h[16];
            #pragma unroll
            for (int j = 0; j < 16; j++) h[j] = sB1[f * 32 + jbase + j];
            #pragma unroll
            for (int i = 0; i < 32; i += 4) {
                float4 e4 = *(const float4*)&sEnc[r1 * 36 + i];
                #pragma unroll
                for (int j = 0; j < 16; j++)
                    h[j] = fmaf(e4.x, w1f[(i + 0) * 32 + jbase + j], h[j]);
                #pragma unroll
                for (int j = 0; j < 16; j++)
                    h[j] = fmaf(e4.y, w1f[(i + 1) * 32 + jbase + j], h[j]);
                #pragma unroll
                for (int j = 0; j < 16; j++)
                    h[j] = fmaf(e4.z, w1f[(i + 2) * 32 + jbase + j], h[j]);
                #pragma unroll
                for (int j = 0; j < 16; j++)
                    h[j] = fmaf(e4.w, w1f[(i + 3) * 32 + jbase + j], h[j]);
            }
            float s1 = 0.f, s2 = 0.f;
            #pragma unroll
            for (int j = 0; j < 16; j++) { s1 += h[j]; s2 = fmaf(h[j], h[j], s2); }
            s1 += __shfl_xor_sync(0xffffffffu, s1, 1);
            s2 += __shfl_xor_sync(0xffffffffu, s2, 1);
            float mean = s1 * (1.f / 32.f);
            float var  = s2 * (1.f / 32.f) - mean * mean;
            float rstd = rsqrtf(var + 1e-5f);
            float wf = g_w[f];
            uint32_t hu[8];
            #pragma unroll
            for (int jj = 0; jj < 8; jj++) {
                float hn0 = fmaf((h[2 * jj]     - mean) * rstd,
                                 sG[f * 32 + jbase + 2 * jj],
                                 sBt[f * 32 + jbase + 2 * jj]);
                float hn1 = fmaf((h[2 * jj + 1] - mean) * rstd,
                                 sG[f * 32 + jbase + 2 * jj + 1],
                                 sBt[f * 32 + jbase + 2 * jj + 1]);
                float a0 = 0.5f * hn0 * (1.f + erff(hn0 * 0.70710678118654752f)) * wf;
                float a1 = 0.5f * hn1 * (1.f + erff(hn1 * 0.70710678118654752f)) * wf;
                hu[jj] = (uint32_t)__half_as_ushort(__float2half(a0)) |
                         ((uint32_t)__half_as_ushort(__float2half(a1)) << 16);
            }
            size_t base = (size_t)(b0 + r1) * 2048 + f * 32 + jbase;
            uint4* ph = (uint4*)(g_A + base);
            ph[0] = make_uint4(hu[0], hu[1], hu[2], hu[3]);
            ph[1] = make_uint4(hu[4], hu[5], hu[6], hu[7]);
        }
        __syncthreads();   // protect sEnc before next f
    }
}

// ---------------------------------------------------------------------------
// Stage 2 GEMM: C = sum_f A.B   (mma.sync fp16, fp32 accum, single pass)
// grid = (4 e-tiles, 512 b-tiles), block = 256 (8 warps, 64x32 each).
// 3-stage cp.async pipeline; A tile 128x32 fp16 (8KB), B tile 32x128 (8KB).
// ---------------------------------------------------------------------------
#define NSTAGE 3
#define STAGE_BYTES 16384
#define B_OFF 8192

__global__ void __launch_bounds__(256, 2)
gemm_kernel(float* __restrict__ out) {
    extern __shared__ char smem[];
    const uint32_t sb = smem_to_u32(smem);
    const int tid = threadIdx.x, wid = tid >> 5, lane = tid & 31;
    const int wm = wid & 1, wn = wid >> 1;
    const int e0 = blockIdx.x * 128, b0 = blockIdx.y * 128;
    const int lr = lane & 15, lc = lane >> 4;

    float d[4][4][4];
    #pragma unroll
    for (int mi = 0; mi < 4; mi++)
        #pragma unroll
        for (int nf = 0; nf < 4; nf++)
            #pragma unroll
            for (int q = 0; q < 4; q++) d[mi][nf][q] = 0.f;

    auto issue_tile = [&](int f) {
        uint32_t s = sb + (f % NSTAGE) * STAGE_BYTES;
        const char* gA0 = (const char*)(g_A + (size_t)b0 * 2048 + f * 32);
        #pragma unroll
        for (int k = 0; k < 2; k++) {
            int c = tid + k * 256;           // 0..511
            int r = c >> 2, off = (c & 3) * 16;
            cp_async16(s + r * 64 + (off ^ ((r & 3) << 4)),
                       gA0 + (size_t)r * 4096 + off);
        }
        const char* gB0 = (const char*)(g_B + (size_t)(f * 32) * E_ + e0);
        uint32_t sB = s + B_OFF;
        #pragma unroll
        for (int k = 0; k < 2; k++) {
            int c = tid + k * 256;           // 0..511
            int kr = c >> 4, off = (c & 15) * 16;
            cp_async16(sB + kr * 256 + (off ^ ((kr & 7) << 4)),
                       gB0 + (size_t)kr * 1024 + off);
        }
    };

    issue_tile(0); CP_COMMIT();
    issue_tile(1); CP_COMMIT();
    issue_tile(2); CP_COMMIT();

    #pragma unroll 1
    for (int f = 0; f < F_; f++) {
        CP_WAIT(2);
        __syncthreads();
        const uint32_t aA = sb + (f % NSTAGE) * STAGE_BYTES;
        const uint32_t aB = aA + B_OFF;

        #pragma unroll
        for (int ks = 0; ks < 2; ks++) {
            uint32_t Ah[4][4], Bf[2][4];

            // load B, A
            const int brow = ks * 16 + lr;
            #pragma unroll
            for (int g = 0; g < 2; g++) {
                int colb = (wn * 32 + g * 16 + lc * 8) * 2;
                ldsm_x4_t(Bf[g], aB + brow * 256 + (colb ^ ((brow & 7) << 4)));
            }
            const int acol = (ks * 16 + lc * 8) * 2;
            #pragma unroll
            for (int mi = 0; mi < 4; mi++) {
                int row = wm * 64 + mi * 16 + lr;
                ldsm_x4(Ah[mi], aA + row * 64 + (acol ^ ((row & 3) << 4)));
            }
            // mma: A . B
            #pragma unroll
            for (int mi = 0; mi < 4; mi++)
                #pragma unroll
                for (int nf = 0; nf < 4; nf++)
                    mma_f16(d[mi][nf][0], d[mi][nf][1], d[mi][nf][2], d[mi][nf][3],
                            Ah[mi][0], Ah[mi][1], Ah[mi][2], Ah[mi][3],
                            Bf[nf >> 1][(nf & 1) * 2], Bf[nf >> 1][(nf & 1) * 2 + 1]);
        }
        __syncthreads();
        if (f + NSTAGE < F_) issue_tile(f + NSTAGE);
        CP_COMMIT();
    }

    // epilogue: add w@b2 bias, store
    #pragma unroll
    for (int mi = 0; mi < 4; mi++) {
        int r0 = b0 + wm * 64 + mi * 16 + (lane >> 2);
        #pragma unroll
        for (int nf = 0; nf < 4; nf++) {
            int col = e0 + wn * 32 + nf * 8 + (lane & 3) * 2;
            float bx = __ldg(&g_wb2[col]), by = __ldg(&g_wb2[col + 1]);
            float2 v0 = make_float2(d[mi][nf][0] + bx, d[mi][nf][1] + by);
            float2 v1 = make_float2(d[mi][nf][2] + bx, d[mi][nf][3] + by);
            *(float2*)(out + (size_t)r0 * E_ + col)       = v0;
            *(float2*)(out + (size_t)(r0 + 8) * E_ + col) = v1;
        }
    }
}

// ---------------------------------------------------------------------------
extern "C" void kernel_launch(void* const* d_in, const int* in_sizes, int n_in,
                              void* d_out, int out_size) {
    const float* bf    = (const float*)d_in[0];   // batch_factors [B,F]
    const float* w_raw = (const float*)d_in[1];   // [F]
    const float* W1    = (const float*)d_in[2];   // [F,L,L]
    const float* b1    = (const float*)d_in[3];   // [F,L]
    const float* gamma = (const float*)d_in[4];   // [F,L]
    const float* beta  = (const float*)d_in[5];   // [F,L]
    const float* W2    = (const float*)d_in[6];   // [F,L,E]
    const float* b2    = (const float*)d_in[7];   // [F,E]
    float* out = (float*)d_out;

    prologue_kernel<<<1, 512>>>(w_raw, b2, out, out_size);
    prep_w2_kernel<<<F_, 512>>>(W2);

    size_t s1_smem = S1_FLOATS * sizeof(float);              // 51.2KB
    cudaFuncSetAttribute(stage1_kernel,
                         cudaFuncAttributeMaxDynamicSharedMemorySize, (int)s1_smem);
    stage1_kernel<<<B_ / 128, 256, s1_smem>>>(bf, W1, b1, gamma, beta);

    size_t g_smem = NSTAGE * STAGE_BYTES;                    // 48KB
    cudaFuncSetAttribute(gemm_kernel,
                         cudaFuncAttributeMaxDynamicSharedMemorySize, (int)g_smem);
    dim3 grid(E_ / 128, B_ / 128);
    gemm_kernel<<<grid, 256, g_smem>>>(out);
}